// round 2
// baseline (speedup 1.0000x reference)
#include <cuda_runtime.h>
#include <cuda_bf16.h>
#include <cstdint>

// Shapes (fixed by the problem)
#define BATCH    2
#define SEQ      2048
#define DMODEL   1024
#define NHEADS   16
#define HEADDIM  64
#define MROWS    (BATCH * SEQ)        // 4096
#define BH       (BATCH * NHEADS)     // 32

// Scratch (device globals — no allocation allowed)
__device__ float g_q[BH * SEQ * HEADDIM];     // [bh][s][dh]
__device__ float g_k[BH * SEQ * HEADDIM];
__device__ float g_v[BH * SEQ * HEADDIM];
__device__ float g_ctx[BATCH * SEQ * DMODEL]; // [b][s][d]

// ---------------------------------------------------------------------------
// GEMM: out = A[M,K] @ W[N,K]^T + bias, M=4096, N=K=1024.
// sel 0/1/2 -> write to g_q/g_k/g_v with [bh][s][dh] layout
// sel 3     -> write plain [M,N] to outext
// Aext == nullptr -> read from g_ctx.
// 128x128 tile, BK=8, 256 threads, 8x8 per-thread microtile.
// ---------------------------------------------------------------------------
__global__ void __launch_bounds__(256) gemm_bias_kernel(
    const float* __restrict__ Aext, const float* __restrict__ W,
    const float* __restrict__ bias, float* __restrict__ outext, int sel)
{
    __shared__ float As[8][128];
    __shared__ float Ws[8][128];

    const float* A = Aext ? Aext : g_ctx;
    float* out;
    if (sel == 0)      out = g_q;
    else if (sel == 1) out = g_k;
    else if (sel == 2) out = g_v;
    else               out = outext;

    const int K = 1024;
    const int bm = blockIdx.y * 128;
    const int bn = blockIdx.x * 128;
    const int tid = threadIdx.x;
    const int tx = tid & 15, ty = tid >> 4;

    const int lr = tid >> 1;           // 0..127
    const int lc = (tid & 1) << 2;     // 0 or 4

    float acc[8][8];
#pragma unroll
    for (int i = 0; i < 8; i++)
#pragma unroll
        for (int j = 0; j < 8; j++) acc[i][j] = 0.f;

    const float* Aptr = A + (size_t)(bm + lr) * K + lc;
    const float* Wptr = W + (size_t)(bn + lr) * K + lc;

    for (int k0 = 0; k0 < K; k0 += 8) {
        float4 a4 = *(const float4*)(Aptr + k0);
        float4 w4 = *(const float4*)(Wptr + k0);
        As[lc + 0][lr] = a4.x; As[lc + 1][lr] = a4.y;
        As[lc + 2][lr] = a4.z; As[lc + 3][lr] = a4.w;
        Ws[lc + 0][lr] = w4.x; Ws[lc + 1][lr] = w4.y;
        Ws[lc + 2][lr] = w4.z; Ws[lc + 3][lr] = w4.w;
        __syncthreads();
#pragma unroll
        for (int kk = 0; kk < 8; kk++) {
            float a[8], w[8];
            *(float4*)&a[0] = *(const float4*)&As[kk][ty * 8];
            *(float4*)&a[4] = *(const float4*)&As[kk][ty * 8 + 4];
            *(float4*)&w[0] = *(const float4*)&Ws[kk][tx * 8];
            *(float4*)&w[4] = *(const float4*)&Ws[kk][tx * 8 + 4];
#pragma unroll
            for (int i = 0; i < 8; i++)
#pragma unroll
                for (int j = 0; j < 8; j++)
                    acc[i][j] = fmaf(a[i], w[j], acc[i][j]);
        }
        __syncthreads();
    }

    const int n0 = bn + tx * 8;
    float bv[8];
    *(float4*)&bv[0] = *(const float4*)(bias + n0);
    *(float4*)&bv[4] = *(const float4*)(bias + n0 + 4);

#pragma unroll
    for (int i = 0; i < 8; i++) {
        const int m = bm + ty * 8 + i;
        float4 r0 = make_float4(acc[i][0] + bv[0], acc[i][1] + bv[1],
                                acc[i][2] + bv[2], acc[i][3] + bv[3]);
        float4 r1 = make_float4(acc[i][4] + bv[4], acc[i][5] + bv[5],
                                acc[i][6] + bv[6], acc[i][7] + bv[7]);
        float* dst;
        if (sel < 3) {
            // [bh][s][dh]: bh = b*16 + h,  n0..n0+7 stays inside one head
            const int b = m >> 11, s = m & 2047;
            const int h = n0 >> 6, dh = n0 & 63;
            dst = out + ((size_t)(b * NHEADS + h)) * (SEQ * HEADDIM)
                      + (size_t)s * HEADDIM + dh;
        } else {
            dst = out + (size_t)m * DMODEL + n0;
        }
        *(float4*)dst       = r0;
        *(float4*)(dst + 4) = r1;
    }
}

// ---------------------------------------------------------------------------
// Causal flash attention over g_q/g_k/g_v -> g_ctx ([B,S,D]).
// CTA: 64 q-rows x full head dim (64). 256 threads = 16x16; 4x4 microtiles.
// Dynamic smem: Qs/Ks/Vt/Ps each 64x68 floats (pad 68 = conflict-free + 16B
// aligned float4), plus per-row m/l state.
// ---------------------------------------------------------------------------
#define AST 68                                  // smem row stride (floats)
#define ATTN_SMEM ((4 * 64 * AST + 128) * 4)    // bytes

__global__ void __launch_bounds__(256) attn_kernel()
{
    extern __shared__ float sm[];
    float* Qs = sm;
    float* Ks = sm + 64 * AST;
    float* Vt = sm + 2 * 64 * AST;
    float* Ps = sm + 3 * 64 * AST;
    float* rm = sm + 4 * 64 * AST;
    float* rl = rm + 64;

    const int qt  = blockIdx.x;          // 0..31
    const int bh  = blockIdx.y;          // 0..31
    const int b   = bh >> 4, h = bh & 15;
    const int tid = threadIdx.x;
    const int tx  = tid & 15, ty = tid >> 4;

    // Load Q tile, pre-scaled by 1/sqrt(64)
    const float* qb = g_q + (size_t)bh * (SEQ * HEADDIM) + (size_t)qt * 64 * HEADDIM;
#pragma unroll
    for (int it = 0; it < 4; it++) {
        const int i = tid + it * 256;
        const int r = i >> 4, c4 = (i & 15) << 2;
        float4 v4 = *(const float4*)(qb + r * HEADDIM + c4);
        v4.x *= 0.125f; v4.y *= 0.125f; v4.z *= 0.125f; v4.w *= 0.125f;
        *(float4*)&Qs[r * AST + c4] = v4;
    }
    if (tid < 64) { rm[tid] = -1e30f; rl[tid] = 0.f; }

    float o[4][4];
#pragma unroll
    for (int i = 0; i < 4; i++)
#pragma unroll
        for (int j = 0; j < 4; j++) o[i][j] = 0.f;

    __syncthreads();

    for (int kt = 0; kt <= qt; kt++) {
        const float* kb = g_k + (size_t)bh * (SEQ * HEADDIM) + (size_t)kt * 64 * HEADDIM;
        const float* vb = g_v + (size_t)bh * (SEQ * HEADDIM) + (size_t)kt * 64 * HEADDIM;
#pragma unroll
        for (int it = 0; it < 4; it++) {
            const int i = tid + it * 256;
            const int r = i >> 4, c4 = (i & 15) << 2;
            *(float4*)&Ks[r * AST + c4] = *(const float4*)(kb + r * HEADDIM + c4);
            float4 vv = *(const float4*)(vb + r * HEADDIM + c4);
            Vt[(c4 + 0) * AST + r] = vv.x;     // transpose: Vt[dh][k]
            Vt[(c4 + 1) * AST + r] = vv.y;
            Vt[(c4 + 2) * AST + r] = vv.z;
            Vt[(c4 + 3) * AST + r] = vv.w;
        }
        __syncthreads();

        // S = (Q/8) K^T  -- 4x4 per thread, float4 along d
        float s[4][4];
#pragma unroll
        for (int i = 0; i < 4; i++)
#pragma unroll
            for (int j = 0; j < 4; j++) s[i][j] = 0.f;
#pragma unroll
        for (int d4 = 0; d4 < 16; d4++) {
            float4 qv[4], kv[4];
#pragma unroll
            for (int i = 0; i < 4; i++)
                qv[i] = *(const float4*)&Qs[(ty * 4 + i) * AST + d4 * 4];
#pragma unroll
            for (int j = 0; j < 4; j++)
                kv[j] = *(const float4*)&Ks[(tx * 4 + j) * AST + d4 * 4];
#pragma unroll
            for (int i = 0; i < 4; i++)
#pragma unroll
                for (int j = 0; j < 4; j++)
                    s[i][j] += qv[i].x * kv[j].x + qv[i].y * kv[j].y
                             + qv[i].z * kv[j].z + qv[i].w * kv[j].w;
        }

        if (kt == qt) {   // causal mask on the diagonal tile only
#pragma unroll
            for (int i = 0; i < 4; i++)
#pragma unroll
                for (int j = 0; j < 4; j++)
                    if (tx * 4 + j > ty * 4 + i) s[i][j] = -1e30f;
        }

        // Online softmax update
        float mnew[4], lsum[4], scl[4];
#pragma unroll
        for (int i = 0; i < 4; i++) {
            float mx = fmaxf(fmaxf(s[i][0], s[i][1]), fmaxf(s[i][2], s[i][3]));
            mx = fmaxf(mx, __shfl_xor_sync(0xffffffffu, mx, 1));
            mx = fmaxf(mx, __shfl_xor_sync(0xffffffffu, mx, 2));
            mx = fmaxf(mx, __shfl_xor_sync(0xffffffffu, mx, 4));
            mx = fmaxf(mx, __shfl_xor_sync(0xffffffffu, mx, 8));
            const float mprev = rm[ty * 4 + i];
            const float mn = fmaxf(mprev, mx);
            float ls = 0.f;
#pragma unroll
            for (int j = 0; j < 4; j++) {
                s[i][j] = __expf(s[i][j] - mn);
                ls += s[i][j];
            }
            ls += __shfl_xor_sync(0xffffffffu, ls, 1);
            ls += __shfl_xor_sync(0xffffffffu, ls, 2);
            ls += __shfl_xor_sync(0xffffffffu, ls, 4);
            ls += __shfl_xor_sync(0xffffffffu, ls, 8);
            mnew[i] = mn; lsum[i] = ls;
            scl[i] = __expf(mprev - mn);
        }

#pragma unroll
        for (int i = 0; i < 4; i++)
            *(float4*)&Ps[(ty * 4 + i) * AST + tx * 4] =
                make_float4(s[i][0], s[i][1], s[i][2], s[i][3]);
#pragma unroll
        for (int i = 0; i < 4; i++)
#pragma unroll
            for (int j = 0; j < 4; j++) o[i][j] *= scl[i];

        __syncwarp();                      // all lanes done reading rm/rl
        if (tx == 0) {
#pragma unroll
            for (int i = 0; i < 4; i++) {
                const int r = ty * 4 + i;
                rm[r] = mnew[i];
                rl[r] = rl[r] * scl[i] + lsum[i];
            }
        }
        __syncthreads();                   // Ps visible, rm/rl ordered

        // O += P @ V  (via Vt, float4 along k)
#pragma unroll
        for (int k4 = 0; k4 < 16; k4++) {
            float4 pv[4], vv[4];
#pragma unroll
            for (int i = 0; i < 4; i++)
                pv[i] = *(const float4*)&Ps[(ty * 4 + i) * AST + k4 * 4];
#pragma unroll
            for (int j = 0; j < 4; j++)
                vv[j] = *(const float4*)&Vt[(tx * 4 + j) * AST + k4 * 4];
#pragma unroll
            for (int i = 0; i < 4; i++)
#pragma unroll
                for (int j = 0; j < 4; j++)
                    o[i][j] += pv[i].x * vv[j].x + pv[i].y * vv[j].y
                             + pv[i].z * vv[j].z + pv[i].w * vv[j].w;
        }
        __syncthreads();                   // before overwriting Ks/Vt/Ps
    }

    // Normalize and write ctx[b][s][h*64+dh]
#pragma unroll
    for (int i = 0; i < 4; i++) {
        const float inv = 1.f / rl[ty * 4 + i];
        const int qg = qt * 64 + ty * 4 + i;
        float* dst = g_ctx + ((size_t)b * SEQ + qg) * DMODEL + h * HEADDIM + tx * 4;
        *(float4*)dst = make_float4(o[i][0] * inv, o[i][1] * inv,
                                    o[i][2] * inv, o[i][3] * inv);
    }
}

// ---------------------------------------------------------------------------
// Launch. Inputs (metadata order): Q,K,V,attn_mask,padding_mask,
// Wq,bq,Wk,bk,Wv,bv,Wo,bo. Masks are the fixed causal/no-padding case and
// are implemented structurally in attn_kernel.
// ---------------------------------------------------------------------------
extern "C" void kernel_launch(void* const* d_in, const int* in_sizes, int n_in,
                              void* d_out, int out_size)
{
    (void)in_sizes; (void)n_in; (void)out_size;
    const float* Q  = (const float*)d_in[0];
    const float* K  = (const float*)d_in[1];
    const float* V  = (const float*)d_in[2];
    const float* Wq = (const float*)d_in[5];
    const float* bq = (const float*)d_in[6];
    const float* Wk = (const float*)d_in[7];
    const float* bk = (const float*)d_in[8];
    const float* Wv = (const float*)d_in[9];
    const float* bv = (const float*)d_in[10];
    const float* Wo = (const float*)d_in[11];
    const float* bo = (const float*)d_in[12];
    float* out = (float*)d_out;

    cudaFuncSetAttribute(attn_kernel,
                         cudaFuncAttributeMaxDynamicSharedMemorySize, ATTN_SMEM);

    dim3 gg(DMODEL / 128, MROWS / 128);   // (8, 32)
    gemm_bias_kernel<<<gg, 256>>>(Q, Wq, bq, nullptr, 0);
    gemm_bias_kernel<<<gg, 256>>>(K, Wk, bk, nullptr, 1);
    gemm_bias_kernel<<<gg, 256>>>(V, Wv, bv, nullptr, 2);
    attn_kernel<<<dim3(SEQ / 64, BH), 256, ATTN_SMEM>>>();
    gemm_bias_kernel<<<gg, 256>>>(nullptr, Wo, bo, out, 3);
}

// round 7
// speedup vs baseline: 2.0737x; 2.0737x over previous
#include <cuda_runtime.h>
#include <cuda_bf16.h>
#include <cstdint>

#define BATCH    2
#define SEQ      2048
#define DMODEL   1024
#define NHEADS   16
#define HEADDIM  64
#define MROWS    (BATCH * SEQ)
#define BH       (BATCH * NHEADS)

__device__ __nv_bfloat16 g_in_hi[3][MROWS * DMODEL];
__device__ __nv_bfloat16 g_in_lo[3][MROWS * DMODEL];
__device__ __nv_bfloat16 g_w_hi[4][DMODEL * DMODEL];
__device__ __nv_bfloat16 g_w_lo[4][DMODEL * DMODEL];
__device__ float g_q[BH * SEQ * HEADDIM];
__device__ float g_k[BH * SEQ * HEADDIM];
__device__ float g_v[BH * SEQ * HEADDIM];
__device__ __nv_bfloat16 g_ctx_hi[MROWS * DMODEL];
__device__ __nv_bfloat16 g_ctx_lo[MROWS * DMODEL];

__device__ __forceinline__ uint32_t smem_u32(const void* p) {
    uint32_t a;
    asm("{ .reg .u64 t; cvta.to.shared.u64 t, %1; cvt.u32.u64 %0, t; }" : "=r"(a) : "l"(p));
    return a;
}
#define CP16(sp, gp)  asm volatile("cp.async.cg.shared.global [%0], [%1], 16;" :: "r"(sp), "l"(gp))
#define CP_COMMIT()   asm volatile("cp.async.commit_group;" ::: "memory")
#define CP_WAIT1()    asm volatile("cp.async.wait_group 1;" ::: "memory")
#define LDSM4(r0, r1, r2, r3, addr) \
    asm volatile("ldmatrix.sync.aligned.m8n8.x4.shared.b16 {%0,%1,%2,%3}, [%4];" \
                 : "=r"(r0), "=r"(r1), "=r"(r2), "=r"(r3) : "r"(addr))
#define MMA16816(c, a, b) \
    asm volatile("mma.sync.aligned.m16n8k16.row.col.f32.bf16.bf16.f32 " \
                 "{%0,%1,%2,%3}, {%4,%5,%6,%7}, {%8,%9}, {%0,%1,%2,%3};" \
                 : "+f"((c)[0]), "+f"((c)[1]), "+f"((c)[2]), "+f"((c)[3]) \
                 : "r"((a)[0]), "r"((a)[1]), "r"((a)[2]), "r"((a)[3]), \
                   "r"((b)[0]), "r"((b)[1]))

// fp32 -> bf16 hi/lo split. which 0..2: inputs, 3..6: weights
__global__ void split_kernel(const float* __restrict__ src, int which, int n)
{
    __nv_bfloat16 *hi, *lo;
    if (which < 3) { hi = g_in_hi[which]; lo = g_in_lo[which]; }
    else           { hi = g_w_hi[which - 3]; lo = g_w_lo[which - 3]; }
    const int stride = gridDim.x * blockDim.x * 4;
    for (int i = (blockIdx.x * blockDim.x + threadIdx.x) * 4; i < n; i += stride) {
        float4 v = *(const float4*)(src + i);
        float f[4] = {v.x, v.y, v.z, v.w};
        __nv_bfloat16 h[4], l[4];
#pragma unroll
        for (int j = 0; j < 4; j++) {
            h[j] = __float2bfloat16(f[j]);
            l[j] = __float2bfloat16(f[j] - __bfloat162float(h[j]));
        }
        *(__nv_bfloat162*)(hi + i)     = __nv_bfloat162(h[0], h[1]);
        *(__nv_bfloat162*)(hi + i + 2) = __nv_bfloat162(h[2], h[3]);
        *(__nv_bfloat162*)(lo + i)     = __nv_bfloat162(l[0], l[1]);
        *(__nv_bfloat162*)(lo + i + 2) = __nv_bfloat162(l[2], l[3]);
    }
}

// ---------------------------------------------------------------------------
// mma.sync bf16 GEMM: D[4096,1024] = A @ W^T + bias, hi/lo 3-segment.
// CTA 128x128, BK=32, 8 warps (warp tile 32x64), 3-stage cp.async pipeline.
// Smem row pitch 40 bf16 (80B): 8 consecutive rows land in 8 distinct 16B
// slots mod 128B -> conflict-free ldmatrix without swizzle.
// ---------------------------------------------------------------------------
#define ASTRIDE 40
#define A_BYTES (128 * ASTRIDE * 2)   // 10240
#define G_STAGE (2 * A_BYTES)         // 20480
#define G_SMEM  (3 * G_STAGE)         // 61440
#define NKIT    96                    // 3 segments x 32 k-chunks

__global__ void __launch_bounds__(256, 1) gemm_mma_kernel(
    const float* __restrict__ bias, float* __restrict__ outext, int sel)
{
    extern __shared__ char smem[];
    const uint32_t sbase = smem_u32(smem);
    const int tid = threadIdx.x;
    const int wid = tid >> 5, lane = tid & 31;
    const int wm = (wid & 3) * 32, wn = (wid >> 2) * 64;
    const int bm = blockIdx.y * 128, bn = blockIdx.x * 128;

    const __nv_bfloat16 *Ahi, *Alo;
    if (sel < 3) { Ahi = g_in_hi[sel]; Alo = g_in_lo[sel]; }
    else         { Ahi = g_ctx_hi;     Alo = g_ctx_lo;     }
    const __nv_bfloat16* Bhi = g_w_hi[sel];
    const __nv_bfloat16* Blo = g_w_lo[sel];

    float c[2][8][4];
#pragma unroll
    for (int i = 0; i < 2; i++)
#pragma unroll
        for (int j = 0; j < 8; j++)
#pragma unroll
            for (int q = 0; q < 4; q++) c[i][j][q] = 0.f;

    auto fill = [&](int kit) {
        const int st = kit % 3, seg = kit >> 5, kk = (kit & 31) * 32;
        const __nv_bfloat16* As = (seg == 2) ? Alo : Ahi;
        const __nv_bfloat16* Bs = (seg == 1) ? Blo : Bhi;
        const uint32_t ab = sbase + st * G_STAGE;
        const uint32_t bb = ab + A_BYTES;
#pragma unroll
        for (int t = 0; t < 2; t++) {
            const int id = tid + t * 256;
            const int r = id >> 2, cc = (id & 3) * 8;
            CP16(ab + (r * ASTRIDE + cc) * 2, As + (size_t)(bm + r) * DMODEL + kk + cc);
            CP16(bb + (r * ASTRIDE + cc) * 2, Bs + (size_t)(bn + r) * DMODEL + kk + cc);
        }
    };

    fill(0); CP_COMMIT();
    fill(1); CP_COMMIT();

    const int lj = lane >> 3, lr = lane & 7;
    const int a_ro = (lj & 1) * 8 + lr, a_co = (lj >> 1) * 8;
    const int b_no = (lj >> 1) * 8 + lr, b_co = (lj & 1) * 8;

    for (int kit = 0; kit < NKIT; kit++) {
        CP_WAIT1();
        __syncthreads();
        if (kit + 2 < NKIT) fill(kit + 2);
        CP_COMMIT();
        const uint32_t ab = sbase + (kit % 3) * G_STAGE;
        const uint32_t bb = ab + A_BYTES;
#pragma unroll
        for (int k16 = 0; k16 < 2; k16++) {
            uint32_t a[2][4];
#pragma unroll
            for (int mt = 0; mt < 2; mt++)
                LDSM4(a[mt][0], a[mt][1], a[mt][2], a[mt][3],
                      ab + ((wm + mt * 16 + a_ro) * ASTRIDE + k16 * 16 + a_co) * 2);
            uint32_t bf[8][2];
#pragma unroll
            for (int np = 0; np < 4; np++) {
                uint32_t r0, r1, r2, r3;
                LDSM4(r0, r1, r2, r3,
                      bb + ((wn + np * 16 + b_no) * ASTRIDE + k16 * 16 + b_co) * 2);
                bf[2 * np][0] = r0; bf[2 * np][1] = r1;
                bf[2 * np + 1][0] = r2; bf[2 * np + 1][1] = r3;
            }
#pragma unroll
            for (int mt = 0; mt < 2; mt++)
#pragma unroll
                for (int nt = 0; nt < 8; nt++)
                    MMA16816(c[mt][nt], a[mt], bf[nt]);
        }
    }

    float* outp = (sel == 0) ? g_q : (sel == 1) ? g_k : (sel == 2) ? g_v : outext;
#pragma unroll
    for (int mt = 0; mt < 2; mt++) {
#pragma unroll
        for (int nt = 0; nt < 8; nt++) {
            const int n0 = bn + wn + nt * 8 + 2 * (lane & 3);
            const float2 bv = *(const float2*)(bias + n0);
#pragma unroll
            for (int half = 0; half < 2; half++) {
                const int m = bm + wm + mt * 16 + (lane >> 2) + half * 8;
                float2 r;
                r.x = c[mt][nt][2 * half]     + bv.x;
                r.y = c[mt][nt][2 * half + 1] + bv.y;
                float* dst;
                if (sel < 3) {
                    const int b = m >> 11, s2 = m & 2047;
                    const int h = n0 >> 6, dh = n0 & 63;
                    dst = outp + ((size_t)(b * NHEADS + h) * SEQ + s2) * HEADDIM + dh;
                } else {
                    dst = outp + (size_t)m * DMODEL + n0;
                }
                *(float2*)dst = r;
            }
        }
    }
}

// ---------------------------------------------------------------------------
// Causal flash attention (fp32), conflict-free smem, exp2 on FMA pipe.
// ---------------------------------------------------------------------------
#define AST 68
#define ATTN_SMEM (4 * 64 * AST * 4)

__device__ __forceinline__ float exp2_fast(float t) {
    t = fmaxf(t, -88.0f);
    const float fl = floorf(t);
    const float f = t - fl;
    float p = 1.5403530e-4f;
    p = fmaf(p, f, 1.3333558e-3f);
    p = fmaf(p, f, 9.6181290e-3f);
    p = fmaf(p, f, 5.5504109e-2f);
    p = fmaf(p, f, 2.4022650e-1f);
    p = fmaf(p, f, 6.9314718e-1f);
    p = fmaf(p, f, 1.0f);
    return __int_as_float(__float_as_int(p) + (((int)fl) << 23));
}

__global__ void __launch_bounds__(256) attn_kernel()
{
    extern __shared__ float sm[];
    float* Qs  = sm;                 // [q][d]
    float* KsT = sm + 64 * AST;      // [d][k]
    float* Vs  = sm + 2 * 64 * AST;  // [k][dh]
    float* Ps  = sm + 3 * 64 * AST;  // [q][k]

    const int qt  = (gridDim.x - 1) - blockIdx.x;   // heavy tiles first
    const int bh  = blockIdx.y;
    const int b   = bh >> 4, h = bh & 15;
    const int tid = threadIdx.x;
    const int tx  = tid & 15, ty = tid >> 4;

    // log2(e)/sqrt(64) = 1.4426950408889634 / 8
    const float qscale = 0.18033688011112042f;
    const float* qb = g_q + (size_t)bh * (SEQ * HEADDIM) + (size_t)qt * 64 * HEADDIM;
#pragma unroll
    for (int it = 0; it < 4; it++) {
        const int i = tid + it * 256;
        const int r = i >> 4, c4 = (i & 15) << 2;
        float4 v = *(const float4*)(qb + r * HEADDIM + c4);
        v.x *= qscale; v.y *= qscale; v.z *= qscale; v.w *= qscale;
        *(float4*)&Qs[r * AST + c4] = v;
    }

    float m_st[4], l_st[4], o[4][4];
#pragma unroll
    for (int i = 0; i < 4; i++) {
        m_st[i] = -1e30f; l_st[i] = 0.f;
#pragma unroll
        for (int j = 0; j < 4; j++) o[i][j] = 0.f;
    }
    __syncthreads();

    for (int kt = 0; kt <= qt; kt++) {
        const float* kb = g_k + (size_t)bh * (SEQ * HEADDIM) + (size_t)kt * 64 * HEADDIM;
        const float* vb = g_v + (size_t)bh * (SEQ * HEADDIM) + (size_t)kt * 64 * HEADDIM;
#pragma unroll
        for (int it = 0; it < 4; it++) {
            const int i = tid + it * 256;
            const int r = i >> 4, c4 = (i & 15) << 2;
            float4 kv = *(const float4*)(kb + r * HEADDIM + c4);
            KsT[(c4 + 0) * AST + r] = kv.x;
            KsT[(c4 + 1) * AST + r] = kv.y;
            KsT[(c4 + 2) * AST + r] = kv.z;
            KsT[(c4 + 3) * AST + r] = kv.w;
            *(float4*)&Vs[r * AST + c4] = *(const float4*)(vb + r * HEADDIM + c4);
        }
        __syncthreads();

        float s[4][4];
#pragma unroll
        for (int i = 0; i < 4; i++)
#pragma unroll
            for (int j = 0; j < 4; j++) s[i][j] = 0.f;
#pragma unroll
        for (int d4 = 0; d4 < 16; d4++) {
            float qv[4][4], kv[4][4];
#pragma unroll
            for (int i = 0; i < 4; i++)
                *(float4*)qv[i] = *(const float4*)&Qs[(ty * 4 + i) * AST + d4 * 4];  // bcast
#pragma unroll
            for (int u = 0; u < 4; u++)
                *(float4*)kv[u] = *(const float4*)&KsT[(d4 * 4 + u) * AST + tx * 4]; // contig
#pragma unroll
            for (int u = 0; u < 4; u++)
#pragma unroll
                for (int i = 0; i < 4; i++)
#pragma unroll
                    for (int j = 0; j < 4; j++)
                        s[i][j] = fmaf(qv[i][u], kv[u][j], s[i][j]);
        }

        if (kt == qt) {
#pragma unroll
            for (int i = 0; i < 4; i++)
#pragma unroll
                for (int j = 0; j < 4; j++)
                    if (tx * 4 + j > ty * 4 + i) s[i][j] = -1e30f;
        }

#pragma unroll
        for (int i = 0; i < 4; i++) {
            float mx = fmaxf(fmaxf(s[i][0], s[i][1]), fmaxf(s[i][2], s[i][3]));
            mx = fmaxf(mx, __shfl_xor_sync(0xffffffffu, mx, 1));
            mx = fmaxf(mx, __shfl_xor_sync(0xffffffffu, mx, 2));
            mx = fmaxf(mx, __shfl_xor_sync(0xffffffffu, mx, 4));
            mx = fmaxf(mx, __shfl_xor_sync(0xffffffffu, mx, 8));
            const float mn = fmaxf(m_st[i], mx);
            float ls = 0.f;
#pragma unroll
            for (int j = 0; j < 4; j++) { s[i][j] = exp2_fast(s[i][j] - mn); ls += s[i][j]; }
            ls += __shfl_xor_sync(0xffffffffu, ls, 1);
            ls += __shfl_xor_sync(0xffffffffu, ls, 2);
            ls += __shfl_xor_sync(0xffffffffu, ls, 4);
            ls += __shfl_xor_sync(0xffffffffu, ls, 8);
            const float scl = exp2_fast(m_st[i] - mn);
            l_st[i] = l_st[i] * scl + ls;
            m_st[i] = mn;
#pragma unroll
            for (int j = 0; j < 4; j++) o[i][j] *= scl;
            *(float4*)&Ps[(ty * 4 + i) * AST + tx * 4] =
                make_float4(s[i][0], s[i][1], s[i][2], s[i][3]);
        }
        __syncthreads();

#pragma unroll
        for (int k4 = 0; k4 < 16; k4++) {
            float pv[4][4], vv[4][4];
#pragma unroll
            for (int i = 0; i < 4; i++)
                *(float4*)pv[i] = *(const float4*)&Ps[(ty * 4 + i) * AST + k4 * 4]; // bcast
#pragma unroll
            for (int u = 0; u < 4; u++)
                *(float4*)vv[u] = *(const float4*)&Vs[(k4 * 4 + u) * AST + tx * 4]; // contig
#pragma unroll
            for (int u = 0; u < 4; u++)
#pragma unroll
                for (int i = 0; i < 4; i++)
#pragma unroll
                    for (int j = 0; j < 4; j++)
                        o[i][j] = fmaf(pv[i][u], vv[u][j], o[i][j]);
        }
        __syncthreads();
    }

#pragma unroll
    for (int i = 0; i < 4; i++) {
        const float inv = 1.f / l_st[i];
        const int qg = qt * 64 + ty * 4 + i;
        const size_t base = ((size_t)b * SEQ + qg) * DMODEL + h * HEADDIM + tx * 4;
        __nv_bfloat16 hv[4], lv[4];
#pragma unroll
        for (int j = 0; j < 4; j++) {
            const float v = o[i][j] * inv;
            hv[j] = __float2bfloat16(v);
            lv[j] = __float2bfloat16(v - __bfloat162float(hv[j]));
        }
        *(__nv_bfloat162*)(g_ctx_hi + base)     = __nv_bfloat162(hv[0], hv[1]);
        *(__nv_bfloat162*)(g_ctx_hi + base + 2) = __nv_bfloat162(hv[2], hv[3]);
        *(__nv_bfloat162*)(g_ctx_lo + base)     = __nv_bfloat162(lv[0], lv[1]);
        *(__nv_bfloat162*)(g_ctx_lo + base + 2) = __nv_bfloat162(lv[2], lv[3]);
    }
}

extern "C" void kernel_launch(void* const* d_in, const int* in_sizes, int n_in,
                              void* d_out, int out_size)
{
    (void)in_sizes; (void)n_in; (void)out_size;
    const float* Q  = (const float*)d_in[0];
    const float* K  = (const float*)d_in[1];
    const float* V  = (const float*)d_in[2];
    const float* Wq = (const float*)d_in[5];
    const float* bq = (const float*)d_in[6];
    const float* Wk = (const float*)d_in[7];
    const float* bk = (const float*)d_in[8];
    const float* Wv = (const float*)d_in[9];
    const float* bv = (const float*)d_in[10];
    const float* Wo = (const float*)d_in[11];
    const float* bo = (const float*)d_in[12];
    float* out = (float*)d_out;

    cudaFuncSetAttribute(gemm_mma_kernel, cudaFuncAttributeMaxDynamicSharedMemorySize, G_SMEM);
    cudaFuncSetAttribute(attn_kernel, cudaFuncAttributeMaxDynamicSharedMemorySize, ATTN_SMEM);

    const int ni = MROWS * DMODEL, nw = DMODEL * DMODEL;
    split_kernel<<<512, 256>>>(Q, 0, ni);
    split_kernel<<<512, 256>>>(K, 1, ni);
    split_kernel<<<512, 256>>>(V, 2, ni);
    split_kernel<<<256, 256>>>(Wq, 3, nw);
    split_kernel<<<256, 256>>>(Wk, 4, nw);
    split_kernel<<<256, 256>>>(Wv, 5, nw);
    split_kernel<<<256, 256>>>(Wo, 6, nw);

    dim3 gg(DMODEL / 128, MROWS / 128);   // (8, 32)
    gemm_mma_kernel<<<gg, 256, G_SMEM>>>(bq, nullptr, 0);
    gemm_mma_kernel<<<gg, 256, G_SMEM>>>(bk, nullptr, 1);
    gemm_mma_kernel<<<gg, 256, G_SMEM>>>(bv, nullptr, 2);
    attn_kernel<<<dim3(SEQ / 64, BH), 256, ATTN_SMEM>>>();
    gemm_mma_kernel<<<gg, 256, G_SMEM>>>(bo, out, 3);
}

// round 8
// speedup vs baseline: 3.9469x; 1.9033x over previous
#include <cuda_runtime.h>
#include <cuda_bf16.h>
#include <cuda_fp16.h>
#include <cstdint>

#define BATCH    2
#define SEQ      2048
#define DMODEL   1024
#define NHEADS   16
#define HEADDIM  64
#define MROWS    (BATCH * SEQ)
#define BH       (BATCH * NHEADS)

__device__ __nv_bfloat16 g_in_hi[3][MROWS * DMODEL];
__device__ __nv_bfloat16 g_in_lo[3][MROWS * DMODEL];
__device__ __nv_bfloat16 g_w_hi[4][DMODEL * DMODEL];
__device__ __nv_bfloat16 g_w_lo[4][DMODEL * DMODEL];
__device__ __half g_qh[BH * SEQ * HEADDIM];   // [bh][s][dh], pre-scaled by log2e/8
__device__ __half g_kh[BH * SEQ * HEADDIM];
__device__ __half g_vh[BH * SEQ * HEADDIM];
__device__ __nv_bfloat16 g_ctx_hi[MROWS * DMODEL];
__device__ __nv_bfloat16 g_ctx_lo[MROWS * DMODEL];

__device__ __forceinline__ uint32_t smem_u32(const void* p) {
    uint32_t a;
    asm("{ .reg .u64 t; cvta.to.shared.u64 t, %1; cvt.u32.u64 %0, t; }" : "=r"(a) : "l"(p));
    return a;
}
#define CP16(sp, gp)  asm volatile("cp.async.cg.shared.global [%0], [%1], 16;" :: "r"(sp), "l"(gp))
#define CP_COMMIT()   asm volatile("cp.async.commit_group;" ::: "memory")
#define CP_WAIT1()    asm volatile("cp.async.wait_group 1;" ::: "memory")
#define LDSM4(r0, r1, r2, r3, addr) \
    asm volatile("ldmatrix.sync.aligned.m8n8.x4.shared.b16 {%0,%1,%2,%3}, [%4];" \
                 : "=r"(r0), "=r"(r1), "=r"(r2), "=r"(r3) : "r"(addr))
#define LDSMT4(r0, r1, r2, r3, addr) \
    asm volatile("ldmatrix.sync.aligned.m8n8.x4.trans.shared.b16 {%0,%1,%2,%3}, [%4];" \
                 : "=r"(r0), "=r"(r1), "=r"(r2), "=r"(r3) : "r"(addr))
#define MMA16816(c, a, b) \
    asm volatile("mma.sync.aligned.m16n8k16.row.col.f32.bf16.bf16.f32 " \
                 "{%0,%1,%2,%3}, {%4,%5,%6,%7}, {%8,%9}, {%0,%1,%2,%3};" \
                 : "+f"((c)[0]), "+f"((c)[1]), "+f"((c)[2]), "+f"((c)[3]) \
                 : "r"((a)[0]), "r"((a)[1]), "r"((a)[2]), "r"((a)[3]), \
                   "r"((b)[0]), "r"((b)[1]))
#define MMAF16(c, a, b) \
    asm volatile("mma.sync.aligned.m16n8k16.row.col.f32.f16.f16.f32 " \
                 "{%0,%1,%2,%3}, {%4,%5,%6,%7}, {%8,%9}, {%0,%1,%2,%3};" \
                 : "+f"((c)[0]), "+f"((c)[1]), "+f"((c)[2]), "+f"((c)[3]) \
                 : "r"((a)[0]), "r"((a)[1]), "r"((a)[2]), "r"((a)[3]), \
                   "r"((b)[0]), "r"((b)[1]))
#define EX2(d, x) asm("ex2.approx.f32 %0, %1;" : "=f"(d) : "f"(x))

__device__ __forceinline__ uint32_t f22h(float a, float b) {
    __half2 h = __floats2half2_rn(a, b);
    return *reinterpret_cast<uint32_t*>(&h);
}

// fp32 -> bf16 hi/lo split. which 0..2: inputs, 3..6: weights
__global__ void split_kernel(const float* __restrict__ src, int which, int n)
{
    __nv_bfloat16 *hi, *lo;
    if (which < 3) { hi = g_in_hi[which]; lo = g_in_lo[which]; }
    else           { hi = g_w_hi[which - 3]; lo = g_w_lo[which - 3]; }
    const int stride = gridDim.x * blockDim.x * 4;
    for (int i = (blockIdx.x * blockDim.x + threadIdx.x) * 4; i < n; i += stride) {
        float4 v = *(const float4*)(src + i);
        float f[4] = {v.x, v.y, v.z, v.w};
        __nv_bfloat16 h[4], l[4];
#pragma unroll
        for (int j = 0; j < 4; j++) {
            h[j] = __float2bfloat16(f[j]);
            l[j] = __float2bfloat16(f[j] - __bfloat162float(h[j]));
        }
        *(__nv_bfloat162*)(hi + i)     = __nv_bfloat162(h[0], h[1]);
        *(__nv_bfloat162*)(hi + i + 2) = __nv_bfloat162(h[2], h[3]);
        *(__nv_bfloat162*)(lo + i)     = __nv_bfloat162(l[0], l[1]);
        *(__nv_bfloat162*)(lo + i + 2) = __nv_bfloat162(l[2], l[3]);
    }
}

// ---------------------------------------------------------------------------
// mma.sync bf16 GEMM (hi/lo 3-segment). sel 0/1/2: out -> fp16 g_qh/g_kh/g_vh
// (sel 0 pre-scaled by log2e/8); sel 3: fp32 out [M,DMODEL].
// ---------------------------------------------------------------------------
#define ASTRIDE 40
#define A_BYTES (128 * ASTRIDE * 2)
#define G_STAGE (2 * A_BYTES)
#define G_SMEM  (3 * G_STAGE)
#define NKIT    96

__global__ void __launch_bounds__(256, 1) gemm_mma_kernel(
    const float* __restrict__ bias, float* __restrict__ outext, int sel)
{
    extern __shared__ char smem[];
    const uint32_t sbase = smem_u32(smem);
    const int tid = threadIdx.x;
    const int wid = tid >> 5, lane = tid & 31;
    const int wm = (wid & 3) * 32, wn = (wid >> 2) * 64;
    const int bm = blockIdx.y * 128, bn = blockIdx.x * 128;

    const __nv_bfloat16 *Ahi, *Alo;
    if (sel < 3) { Ahi = g_in_hi[sel]; Alo = g_in_lo[sel]; }
    else         { Ahi = g_ctx_hi;     Alo = g_ctx_lo;     }
    const __nv_bfloat16* Bhi = g_w_hi[sel];
    const __nv_bfloat16* Blo = g_w_lo[sel];

    float c[2][8][4];
#pragma unroll
    for (int i = 0; i < 2; i++)
#pragma unroll
        for (int j = 0; j < 8; j++)
#pragma unroll
            for (int q = 0; q < 4; q++) c[i][j][q] = 0.f;

    auto fill = [&](int kit) {
        const int st = kit % 3, seg = kit >> 5, kk = (kit & 31) * 32;
        const __nv_bfloat16* As = (seg == 2) ? Alo : Ahi;
        const __nv_bfloat16* Bs = (seg == 1) ? Blo : Bhi;
        const uint32_t ab = sbase + st * G_STAGE;
        const uint32_t bb = ab + A_BYTES;
#pragma unroll
        for (int t = 0; t < 2; t++) {
            const int id = tid + t * 256;
            const int r = id >> 2, cc = (id & 3) * 8;
            CP16(ab + (r * ASTRIDE + cc) * 2, As + (size_t)(bm + r) * DMODEL + kk + cc);
            CP16(bb + (r * ASTRIDE + cc) * 2, Bs + (size_t)(bn + r) * DMODEL + kk + cc);
        }
    };

    fill(0); CP_COMMIT();
    fill(1); CP_COMMIT();

    const int lj = lane >> 3, lr = lane & 7;
    const int a_ro = (lj & 1) * 8 + lr, a_co = (lj >> 1) * 8;
    const int b_no = (lj >> 1) * 8 + lr, b_co = (lj & 1) * 8;

    for (int kit = 0; kit < NKIT; kit++) {
        CP_WAIT1();
        __syncthreads();
        if (kit + 2 < NKIT) fill(kit + 2);
        CP_COMMIT();
        const uint32_t ab = sbase + (kit % 3) * G_STAGE;
        const uint32_t bb = ab + A_BYTES;
#pragma unroll
        for (int k16 = 0; k16 < 2; k16++) {
            uint32_t a[2][4];
#pragma unroll
            for (int mt = 0; mt < 2; mt++)
                LDSM4(a[mt][0], a[mt][1], a[mt][2], a[mt][3],
                      ab + ((wm + mt * 16 + a_ro) * ASTRIDE + k16 * 16 + a_co) * 2);
            uint32_t bf[8][2];
#pragma unroll
            for (int np = 0; np < 4; np++) {
                uint32_t r0, r1, r2, r3;
                LDSM4(r0, r1, r2, r3,
                      bb + ((wn + np * 16 + b_no) * ASTRIDE + k16 * 16 + b_co) * 2);
                bf[2 * np][0] = r0; bf[2 * np][1] = r1;
                bf[2 * np + 1][0] = r2; bf[2 * np + 1][1] = r3;
            }
#pragma unroll
            for (int mt = 0; mt < 2; mt++)
#pragma unroll
                for (int nt = 0; nt < 8; nt++)
                    MMA16816(c[mt][nt], a[mt], bf[nt]);
        }
    }

    const float oscale = (sel == 0) ? 0.18033688011112042f : 1.0f;  // log2e/8 folded into Q
    __half* outh = (sel == 0) ? g_qh : (sel == 1) ? g_kh : g_vh;
#pragma unroll
    for (int mt = 0; mt < 2; mt++) {
#pragma unroll
        for (int nt = 0; nt < 8; nt++) {
            const int n0 = bn + wn + nt * 8 + 2 * (lane & 3);
            const float2 bv = *(const float2*)(bias + n0);
#pragma unroll
            for (int half = 0; half < 2; half++) {
                const int m = bm + wm + mt * 16 + (lane >> 2) + half * 8;
                const float rx = c[mt][nt][2 * half]     + bv.x;
                const float ry = c[mt][nt][2 * half + 1] + bv.y;
                if (sel < 3) {
                    const int b = m >> 11, s2 = m & 2047;
                    const int h = n0 >> 6, dh = n0 & 63;
                    __half2 hv = __floats2half2_rn(rx * oscale, ry * oscale);
                    *(__half2*)(outh + ((size_t)(b * NHEADS + h) * SEQ + s2) * HEADDIM + dh) = hv;
                } else {
                    *(float2*)(outext + (size_t)m * DMODEL + n0) = make_float2(rx, ry);
                }
            }
        }
    }
}

// ---------------------------------------------------------------------------
// fp16 tensor-core causal flash attention (FA2 sm80 pattern).
// CTA: 64 q-rows, 4 warps (warp = m16 x full 64). P stays in registers.
// smem: Q + double-buffered K/V, stride 72 halves (144B, conflict-free).
// ---------------------------------------------------------------------------
#define SST 72
#define ATTN_SMEM (5 * 64 * SST * 2)   // 46080 B

__global__ void __launch_bounds__(128) attn_kernel()
{
    extern __shared__ __half smh[];
    const uint32_t sbase = smem_u32(smh);
    const int qt  = (gridDim.x - 1) - blockIdx.x;   // heavy tiles first
    const int bh  = blockIdx.y;
    const int b   = bh >> 4, h = bh & 15;
    const int tid = threadIdx.x;
    const int w   = tid >> 5, lane = tid & 31;
    const int lj = lane >> 3, lr = lane & 7;
    const int a_ro = (lj & 1) * 8 + lr, a_co = (lj >> 1) * 8;
    const int b_no = (lj >> 1) * 8 + lr, b_co = (lj & 1) * 8;
    const int q4 = lane >> 2, q2 = 2 * (lane & 3);

    const size_t kvoff = (size_t)bh * (SEQ * HEADDIM);
    // Q tile (one group with KV0)
    {
        const __half* qg = g_qh + kvoff + (size_t)qt * 64 * HEADDIM;
#pragma unroll
        for (int it = 0; it < 4; it++) {
            const int id = tid + it * 128, r = id >> 3, ch = id & 7;
            CP16(sbase + (r * SST + ch * 8) * 2, qg + r * 64 + ch * 8);
        }
    }
    auto fillKV = [&](int kt, int st) {
        const __half* kb = g_kh + kvoff + (size_t)kt * 64 * HEADDIM;
        const __half* vb = g_vh + kvoff + (size_t)kt * 64 * HEADDIM;
        const uint32_t kd = sbase + (4608 + st * 9216) * 2;
        const uint32_t vd = sbase + (9216 + st * 9216) * 2;
#pragma unroll
        for (int it = 0; it < 4; it++) {
            const int id = tid + it * 128, r = id >> 3, ch = id & 7;
            CP16(kd + (r * SST + ch * 8) * 2, kb + r * 64 + ch * 8);
            CP16(vd + (r * SST + ch * 8) * 2, vb + r * 64 + ch * 8);
        }
    };
    fillKV(0, 0);
    CP_COMMIT();

    float O[8][4];
#pragma unroll
    for (int t = 0; t < 8; t++)
#pragma unroll
        for (int i = 0; i < 4; i++) O[t][i] = 0.f;
    float m0 = -1e30f, m1 = -1e30f, l0 = 0.f, l1 = 0.f;

    for (int kt = 0; kt <= qt; kt++) {
        const int st = kt & 1;
        if (kt < qt) fillKV(kt + 1, st ^ 1);
        CP_COMMIT();
        CP_WAIT1();
        __syncthreads();
        const uint32_t Kb = sbase + (4608 + st * 9216) * 2;
        const uint32_t Vb = sbase + (9216 + st * 9216) * 2;

        // S = Q K^T  (Q pre-scaled by log2e/8 -> base-2 scores)
        float S[8][4];
#pragma unroll
        for (int t = 0; t < 8; t++)
#pragma unroll
            for (int i = 0; i < 4; i++) S[t][i] = 0.f;
#pragma unroll
        for (int kk = 0; kk < 4; kk++) {
            uint32_t a[4];
            LDSM4(a[0], a[1], a[2], a[3],
                  sbase + ((w * 16 + a_ro) * SST + kk * 16 + a_co) * 2);
#pragma unroll
            for (int np = 0; np < 4; np++) {
                uint32_t r0, r1, r2, r3;
                LDSM4(r0, r1, r2, r3,
                      Kb + ((np * 16 + b_no) * SST + kk * 16 + b_co) * 2);
                uint32_t bA[2] = {r0, r1}, bB[2] = {r2, r3};
                MMAF16(S[2 * np], a, bA);
                MMAF16(S[2 * np + 1], a, bB);
            }
        }

        if (kt == qt) {   // causal mask, diagonal tile only
            const int row0 = w * 16 + q4, row1 = row0 + 8;
#pragma unroll
            for (int t = 0; t < 8; t++) {
                const int c0 = t * 8 + q2;
                if (c0     > row0) S[t][0] = -1e30f;
                if (c0 + 1 > row0) S[t][1] = -1e30f;
                if (c0     > row1) S[t][2] = -1e30f;
                if (c0 + 1 > row1) S[t][3] = -1e30f;
            }
        }

        // online softmax (2 rows per thread; quad holds full row)
        float mx0 = -1e30f, mx1 = -1e30f;
#pragma unroll
        for (int t = 0; t < 8; t++) {
            mx0 = fmaxf(mx0, fmaxf(S[t][0], S[t][1]));
            mx1 = fmaxf(mx1, fmaxf(S[t][2], S[t][3]));
        }
        mx0 = fmaxf(mx0, __shfl_xor_sync(0xffffffffu, mx0, 1));
        mx0 = fmaxf(mx0, __shfl_xor_sync(0xffffffffu, mx0, 2));
        mx1 = fmaxf(mx1, __shfl_xor_sync(0xffffffffu, mx1, 1));
        mx1 = fmaxf(mx1, __shfl_xor_sync(0xffffffffu, mx1, 2));
        const float nm0 = fmaxf(m0, mx0), nm1 = fmaxf(m1, mx1);
        float scl0, scl1;
        EX2(scl0, m0 - nm0);
        EX2(scl1, m1 - nm1);
        m0 = nm0; m1 = nm1;
        float ls0 = 0.f, ls1 = 0.f;
#pragma unroll
        for (int t = 0; t < 8; t++) {
            EX2(S[t][0], S[t][0] - m0); ls0 += S[t][0];
            EX2(S[t][1], S[t][1] - m0); ls0 += S[t][1];
            EX2(S[t][2], S[t][2] - m1); ls1 += S[t][2];
            EX2(S[t][3], S[t][3] - m1); ls1 += S[t][3];
        }
        ls0 += __shfl_xor_sync(0xffffffffu, ls0, 1);
        ls0 += __shfl_xor_sync(0xffffffffu, ls0, 2);
        ls1 += __shfl_xor_sync(0xffffffffu, ls1, 1);
        ls1 += __shfl_xor_sync(0xffffffffu, ls1, 2);
        l0 = l0 * scl0 + ls0;
        l1 = l1 * scl1 + ls1;
#pragma unroll
        for (int t = 0; t < 8; t++) {
            O[t][0] *= scl0; O[t][1] *= scl0;
            O[t][2] *= scl1; O[t][3] *= scl1;
        }

        // O += P V  (P converted in registers; V via ldmatrix.trans)
#pragma unroll
        for (int cch = 0; cch < 4; cch++) {
            uint32_t a[4];
            a[0] = f22h(S[2 * cch][0],     S[2 * cch][1]);
            a[1] = f22h(S[2 * cch][2],     S[2 * cch][3]);
            a[2] = f22h(S[2 * cch + 1][0], S[2 * cch + 1][1]);
            a[3] = f22h(S[2 * cch + 1][2], S[2 * cch + 1][3]);
#pragma unroll
            for (int np = 0; np < 4; np++) {
                uint32_t r0, r1, r2, r3;
                LDSMT4(r0, r1, r2, r3,
                       Vb + ((cch * 16 + (lj & 1) * 8 + lr) * SST + np * 16 + (lj >> 1) * 8) * 2);
                uint32_t bA[2] = {r0, r1}, bB[2] = {r2, r3};
                MMAF16(O[2 * np], a, bA);
                MMAF16(O[2 * np + 1], a, bB);
            }
        }
        __syncthreads();
    }

    // normalize, write ctx hi/lo bf16
    const float inv0 = 1.f / l0, inv1 = 1.f / l1;
    const int r0g = qt * 64 + w * 16 + q4, r1g = r0g + 8;
#pragma unroll
    for (int t = 0; t < 8; t++) {
        const int dh = t * 8 + q2;
        const size_t base0 = ((size_t)b * SEQ + r0g) * DMODEL + h * HEADDIM + dh;
        const size_t base1 = ((size_t)b * SEQ + r1g) * DMODEL + h * HEADDIM + dh;
        float v0 = O[t][0] * inv0, v1 = O[t][1] * inv0;
        float v2 = O[t][2] * inv1, v3 = O[t][3] * inv1;
        __nv_bfloat16 h0 = __float2bfloat16(v0), h1 = __float2bfloat16(v1);
        __nv_bfloat16 h2 = __float2bfloat16(v2), h3 = __float2bfloat16(v3);
        *(__nv_bfloat162*)(g_ctx_hi + base0) = __nv_bfloat162(h0, h1);
        *(__nv_bfloat162*)(g_ctx_hi + base1) = __nv_bfloat162(h2, h3);
        *(__nv_bfloat162*)(g_ctx_lo + base0) = __nv_bfloat162(
            __float2bfloat16(v0 - __bfloat162float(h0)),
            __float2bfloat16(v1 - __bfloat162float(h1)));
        *(__nv_bfloat162*)(g_ctx_lo + base1) = __nv_bfloat162(
            __float2bfloat16(v2 - __bfloat162float(h2)),
            __float2bfloat16(v3 - __bfloat162float(h3)));
    }
}

extern "C" void kernel_launch(void* const* d_in, const int* in_sizes, int n_in,
                              void* d_out, int out_size)
{
    (void)in_sizes; (void)n_in; (void)out_size;
    const float* Q  = (const float*)d_in[0];
    const float* K  = (const float*)d_in[1];
    const float* V  = (const float*)d_in[2];
    const float* Wq = (const float*)d_in[5];
    const float* bq = (const float*)d_in[6];
    const float* Wk = (const float*)d_in[7];
    const float* bk = (const float*)d_in[8];
    const float* Wv = (const float*)d_in[9];
    const float* bv = (const float*)d_in[10];
    const float* Wo = (const float*)d_in[11];
    const float* bo = (const float*)d_in[12];
    float* out = (float*)d_out;

    cudaFuncSetAttribute(gemm_mma_kernel, cudaFuncAttributeMaxDynamicSharedMemorySize, G_SMEM);
    cudaFuncSetAttribute(attn_kernel, cudaFuncAttributeMaxDynamicSharedMemorySize, ATTN_SMEM);

    const int ni = MROWS * DMODEL, nw = DMODEL * DMODEL;
    split_kernel<<<512, 256>>>(Q, 0, ni);
    split_kernel<<<512, 256>>>(K, 1, ni);
    split_kernel<<<512, 256>>>(V, 2, ni);
    split_kernel<<<256, 256>>>(Wq, 3, nw);
    split_kernel<<<256, 256>>>(Wk, 4, nw);
    split_kernel<<<256, 256>>>(Wv, 5, nw);
    split_kernel<<<256, 256>>>(Wo, 6, nw);

    dim3 gg(DMODEL / 128, MROWS / 128);   // (8, 32)
    gemm_mma_kernel<<<gg, 256, G_SMEM>>>(bq, nullptr, 0);
    gemm_mma_kernel<<<gg, 256, G_SMEM>>>(bk, nullptr, 1);
    gemm_mma_kernel<<<gg, 256, G_SMEM>>>(bv, nullptr, 2);
    attn_kernel<<<dim3(SEQ / 64, BH), 128, ATTN_SMEM>>>();
    gemm_mma_kernel<<<gg, 256, G_SMEM>>>(bo, out, 3);
}

// round 9
// speedup vs baseline: 5.9592x; 1.5098x over previous
#include <cuda_runtime.h>
#include <cuda_fp16.h>
#include <cstdint>

#define BATCH    2
#define SEQ      2048
#define DMODEL   1024
#define NHEADS   16
#define HEADDIM  64
#define MROWS    (BATCH * SEQ)
#define BH       (BATCH * NHEADS)

__device__ __half g_in_hi[3][MROWS * DMODEL];
__device__ __half g_in_lo[3][MROWS * DMODEL];
__device__ __half g_w[4][DMODEL * DMODEL];
__device__ __half g_qh[BH * SEQ * HEADDIM];   // [bh][s][dh], pre-scaled by log2e/8
__device__ __half g_kh[BH * SEQ * HEADDIM];
__device__ __half g_vh[BH * SEQ * HEADDIM];
__device__ __half g_ctx_hi[MROWS * DMODEL];
__device__ __half g_ctx_lo[MROWS * DMODEL];

__device__ __forceinline__ uint32_t smem_u32(const void* p) {
    uint32_t a;
    asm("{ .reg .u64 t; cvta.to.shared.u64 t, %1; cvt.u32.u64 %0, t; }" : "=r"(a) : "l"(p));
    return a;
}
#define CP16(sp, gp)  asm volatile("cp.async.cg.shared.global [%0], [%1], 16;" :: "r"(sp), "l"(gp))
#define CP_COMMIT()   asm volatile("cp.async.commit_group;" ::: "memory")
#define CP_WAIT1()    asm volatile("cp.async.wait_group 1;" ::: "memory")
#define LDSM4(r0, r1, r2, r3, addr) \
    asm volatile("ldmatrix.sync.aligned.m8n8.x4.shared.b16 {%0,%1,%2,%3}, [%4];" \
                 : "=r"(r0), "=r"(r1), "=r"(r2), "=r"(r3) : "r"(addr))
#define LDSMT4(r0, r1, r2, r3, addr) \
    asm volatile("ldmatrix.sync.aligned.m8n8.x4.trans.shared.b16 {%0,%1,%2,%3}, [%4];" \
                 : "=r"(r0), "=r"(r1), "=r"(r2), "=r"(r3) : "r"(addr))
#define MMAF16(c, a, b) \
    asm volatile("mma.sync.aligned.m16n8k16.row.col.f32.f16.f16.f32 " \
                 "{%0,%1,%2,%3}, {%4,%5,%6,%7}, {%8,%9}, {%0,%1,%2,%3};" \
                 : "+f"((c)[0]), "+f"((c)[1]), "+f"((c)[2]), "+f"((c)[3]) \
                 : "r"((a)[0]), "r"((a)[1]), "r"((a)[2]), "r"((a)[3]), \
                   "r"((b)[0]), "r"((b)[1]))
#define EX2(d, x) asm("ex2.approx.f32 %0, %1;" : "=f"(d) : "f"(x))

__device__ __forceinline__ uint32_t f22h(float a, float b) {
    __half2 h = __floats2half2_rn(a, b);
    return *reinterpret_cast<uint32_t*>(&h);
}

// which 0..2: inputs -> fp16 hi/lo split; 3..6: weights -> single fp16
__global__ void split_kernel(const float* __restrict__ src, int which, int n)
{
    const int stride = gridDim.x * blockDim.x * 4;
    if (which < 3) {
        __half* hi = g_in_hi[which];
        __half* lo = g_in_lo[which];
        for (int i = (blockIdx.x * blockDim.x + threadIdx.x) * 4; i < n; i += stride) {
            float4 v = *(const float4*)(src + i);
            float f[4] = {v.x, v.y, v.z, v.w};
            __half h[4], l[4];
#pragma unroll
            for (int j = 0; j < 4; j++) {
                h[j] = __float2half_rn(f[j]);
                l[j] = __float2half_rn(f[j] - __half2float(h[j]));
            }
            *(__half2*)(hi + i)     = __half2(h[0], h[1]);
            *(__half2*)(hi + i + 2) = __half2(h[2], h[3]);
            *(__half2*)(lo + i)     = __half2(l[0], l[1]);
            *(__half2*)(lo + i + 2) = __half2(l[2], l[3]);
        }
    } else {
        __half* w = g_w[which - 3];
        for (int i = (blockIdx.x * blockDim.x + threadIdx.x) * 4; i < n; i += stride) {
            float4 v = *(const float4*)(src + i);
            *(__half2*)(w + i)     = __floats2half2_rn(v.x, v.y);
            *(__half2*)(w + i + 2) = __floats2half2_rn(v.z, v.w);
        }
    }
}

// ---------------------------------------------------------------------------
// fp16 2-segment GEMM: D = (Ahi + Alo) @ Wh^T + bias.
// Per k-chunk: load {Ahi, Alo, B} tiles once; both segment MMAs reuse the
// same B fragments and accumulate into one fp32 accumulator.
// CTA 128x128, BK=32, 8 warps, 3-stage cp.async pipeline.
// ---------------------------------------------------------------------------
#define ASTRIDE 40
#define A_BYTES (128 * ASTRIDE * 2)   // 10240
#define G_STAGE (3 * A_BYTES)         // 30720: Ahi | Alo | B
#define G_SMEM  (3 * G_STAGE)         // 92160
#define NKIT    32

__global__ void __launch_bounds__(256, 1) gemm_mma_kernel(
    const float* __restrict__ bias, float* __restrict__ outext, int sel)
{
    extern __shared__ char smem[];
    const uint32_t sbase = smem_u32(smem);
    const int tid = threadIdx.x;
    const int wid = tid >> 5, lane = tid & 31;
    const int wm = (wid & 3) * 32, wn = (wid >> 2) * 64;
    const int bm = blockIdx.y * 128, bn = blockIdx.x * 128;

    const __half *Ahi, *Alo;
    if (sel < 3) { Ahi = g_in_hi[sel]; Alo = g_in_lo[sel]; }
    else         { Ahi = g_ctx_hi;     Alo = g_ctx_lo;     }
    const __half* Bh = g_w[sel];

    float c[2][8][4];
#pragma unroll
    for (int i = 0; i < 2; i++)
#pragma unroll
        for (int j = 0; j < 8; j++)
#pragma unroll
            for (int q = 0; q < 4; q++) c[i][j][q] = 0.f;

    auto fill = [&](int kit) {
        const int st = kit % 3, kk = kit * 32;
        const uint32_t hb = sbase + st * G_STAGE;
        const uint32_t lb = hb + A_BYTES;
        const uint32_t bb = hb + 2 * A_BYTES;
#pragma unroll
        for (int t = 0; t < 2; t++) {
            const int id = tid + t * 256;
            const int r = id >> 2, cc = (id & 3) * 8;
            const uint32_t so = (r * ASTRIDE + cc) * 2;
            CP16(hb + so, Ahi + (size_t)(bm + r) * DMODEL + kk + cc);
            CP16(lb + so, Alo + (size_t)(bm + r) * DMODEL + kk + cc);
            CP16(bb + so, Bh  + (size_t)(bn + r) * DMODEL + kk + cc);
        }
    };

    fill(0); CP_COMMIT();
    fill(1); CP_COMMIT();

    const int lj = lane >> 3, lr = lane & 7;
    const int a_ro = (lj & 1) * 8 + lr, a_co = (lj >> 1) * 8;
    const int b_no = (lj >> 1) * 8 + lr, b_co = (lj & 1) * 8;

    for (int kit = 0; kit < NKIT; kit++) {
        CP_WAIT1();
        __syncthreads();
        if (kit + 2 < NKIT) fill(kit + 2);
        CP_COMMIT();
        const uint32_t hb = sbase + (kit % 3) * G_STAGE;
        const uint32_t lb = hb + A_BYTES;
        const uint32_t bb = hb + 2 * A_BYTES;
#pragma unroll
        for (int k16 = 0; k16 < 2; k16++) {
            uint32_t ah[2][4], al[2][4];
#pragma unroll
            for (int mt = 0; mt < 2; mt++) {
                const uint32_t ro = ((wm + mt * 16 + a_ro) * ASTRIDE + k16 * 16 + a_co) * 2;
                LDSM4(ah[mt][0], ah[mt][1], ah[mt][2], ah[mt][3], hb + ro);
                LDSM4(al[mt][0], al[mt][1], al[mt][2], al[mt][3], lb + ro);
            }
            uint32_t bf[8][2];
#pragma unroll
            for (int np = 0; np < 4; np++) {
                uint32_t r0, r1, r2, r3;
                LDSM4(r0, r1, r2, r3,
                      bb + ((wn + np * 16 + b_no) * ASTRIDE + k16 * 16 + b_co) * 2);
                bf[2 * np][0] = r0; bf[2 * np][1] = r1;
                bf[2 * np + 1][0] = r2; bf[2 * np + 1][1] = r3;
            }
#pragma unroll
            for (int mt = 0; mt < 2; mt++)
#pragma unroll
                for (int nt = 0; nt < 8; nt++) {
                    MMAF16(c[mt][nt], ah[mt], bf[nt]);
                    MMAF16(c[mt][nt], al[mt], bf[nt]);
                }
        }
    }

    const float oscale = (sel == 0) ? 0.18033688011112042f : 1.0f;  // log2e/8 folded into Q
    __half* outh = (sel == 0) ? g_qh : (sel == 1) ? g_kh : g_vh;
#pragma unroll
    for (int mt = 0; mt < 2; mt++) {
#pragma unroll
        for (int nt = 0; nt < 8; nt++) {
            const int n0 = bn + wn + nt * 8 + 2 * (lane & 3);
            const float2 bv = *(const float2*)(bias + n0);
#pragma unroll
            for (int half = 0; half < 2; half++) {
                const int m = bm + wm + mt * 16 + (lane >> 2) + half * 8;
                const float rx = c[mt][nt][2 * half]     + bv.x;
                const float ry = c[mt][nt][2 * half + 1] + bv.y;
                if (sel < 3) {
                    const int b = m >> 11, s2 = m & 2047;
                    const int h = n0 >> 6, dh = n0 & 63;
                    __half2 hv = __floats2half2_rn(rx * oscale, ry * oscale);
                    *(__half2*)(outh + ((size_t)(b * NHEADS + h) * SEQ + s2) * HEADDIM + dh) = hv;
                } else {
                    *(float2*)(outext + (size_t)m * DMODEL + n0) = make_float2(rx, ry);
                }
            }
        }
    }
}

// ---------------------------------------------------------------------------
// fp16 tensor-core causal flash attention (unchanged from round 8 winner).
// ---------------------------------------------------------------------------
#define SST 72
#define ATTN_SMEM (5 * 64 * SST * 2)   // 46080 B

__global__ void __launch_bounds__(128) attn_kernel()
{
    extern __shared__ __half smh[];
    const uint32_t sbase = smem_u32(smh);
    const int qt  = (gridDim.x - 1) - blockIdx.x;   // heavy tiles first
    const int bh  = blockIdx.y;
    const int b   = bh >> 4, h = bh & 15;
    const int tid = threadIdx.x;
    const int w   = tid >> 5, lane = tid & 31;
    const int lj = lane >> 3, lr = lane & 7;
    const int a_ro = (lj & 1) * 8 + lr, a_co = (lj >> 1) * 8;
    const int b_no = (lj >> 1) * 8 + lr, b_co = (lj & 1) * 8;
    const int q4 = lane >> 2, q2 = 2 * (lane & 3);

    const size_t kvoff = (size_t)bh * (SEQ * HEADDIM);
    {
        const __half* qg = g_qh + kvoff + (size_t)qt * 64 * HEADDIM;
#pragma unroll
        for (int it = 0; it < 4; it++) {
            const int id = tid + it * 128, r = id >> 3, ch = id & 7;
            CP16(sbase + (r * SST + ch * 8) * 2, qg + r * 64 + ch * 8);
        }
    }
    auto fillKV = [&](int kt, int st) {
        const __half* kb = g_kh + kvoff + (size_t)kt * 64 * HEADDIM;
        const __half* vb = g_vh + kvoff + (size_t)kt * 64 * HEADDIM;
        const uint32_t kd = sbase + (4608 + st * 9216) * 2;
        const uint32_t vd = sbase + (9216 + st * 9216) * 2;
#pragma unroll
        for (int it = 0; it < 4; it++) {
            const int id = tid + it * 128, r = id >> 3, ch = id & 7;
            CP16(kd + (r * SST + ch * 8) * 2, kb + r * 64 + ch * 8);
            CP16(vd + (r * SST + ch * 8) * 2, vb + r * 64 + ch * 8);
        }
    };
    fillKV(0, 0);
    CP_COMMIT();

    float O[8][4];
#pragma unroll
    for (int t = 0; t < 8; t++)
#pragma unroll
        for (int i = 0; i < 4; i++) O[t][i] = 0.f;
    float m0 = -1e30f, m1 = -1e30f, l0 = 0.f, l1 = 0.f;

    for (int kt = 0; kt <= qt; kt++) {
        const int st = kt & 1;
        if (kt < qt) fillKV(kt + 1, st ^ 1);
        CP_COMMIT();
        CP_WAIT1();
        __syncthreads();
        const uint32_t Kb = sbase + (4608 + st * 9216) * 2;
        const uint32_t Vb = sbase + (9216 + st * 9216) * 2;

        float S[8][4];
#pragma unroll
        for (int t = 0; t < 8; t++)
#pragma unroll
            for (int i = 0; i < 4; i++) S[t][i] = 0.f;
#pragma unroll
        for (int kk = 0; kk < 4; kk++) {
            uint32_t a[4];
            LDSM4(a[0], a[1], a[2], a[3],
                  sbase + ((w * 16 + a_ro) * SST + kk * 16 + a_co) * 2);
#pragma unroll
            for (int np = 0; np < 4; np++) {
                uint32_t r0, r1, r2, r3;
                LDSM4(r0, r1, r2, r3,
                      Kb + ((np * 16 + b_no) * SST + kk * 16 + b_co) * 2);
                uint32_t bA[2] = {r0, r1}, bB[2] = {r2, r3};
                MMAF16(S[2 * np], a, bA);
                MMAF16(S[2 * np + 1], a, bB);
            }
        }

        if (kt == qt) {
            const int row0 = w * 16 + q4, row1 = row0 + 8;
#pragma unroll
            for (int t = 0; t < 8; t++) {
                const int c0 = t * 8 + q2;
                if (c0     > row0) S[t][0] = -1e30f;
                if (c0 + 1 > row0) S[t][1] = -1e30f;
                if (c0     > row1) S[t][2] = -1e30f;
                if (c0 + 1 > row1) S[t][3] = -1e30f;
            }
        }

        float mx0 = -1e30f, mx1 = -1e30f;
#pragma unroll
        for (int t = 0; t < 8; t++) {
            mx0 = fmaxf(mx0, fmaxf(S[t][0], S[t][1]));
            mx1 = fmaxf(mx1, fmaxf(S[t][2], S[t][3]));
        }
        mx0 = fmaxf(mx0, __shfl_xor_sync(0xffffffffu, mx0, 1));
        mx0 = fmaxf(mx0, __shfl_xor_sync(0xffffffffu, mx0, 2));
        mx1 = fmaxf(mx1, __shfl_xor_sync(0xffffffffu, mx1, 1));
        mx1 = fmaxf(mx1, __shfl_xor_sync(0xffffffffu, mx1, 2));
        const float nm0 = fmaxf(m0, mx0), nm1 = fmaxf(m1, mx1);
        float scl0, scl1;
        EX2(scl0, m0 - nm0);
        EX2(scl1, m1 - nm1);
        m0 = nm0; m1 = nm1;
        float ls0 = 0.f, ls1 = 0.f;
#pragma unroll
        for (int t = 0; t < 8; t++) {
            EX2(S[t][0], S[t][0] - m0); ls0 += S[t][0];
            EX2(S[t][1], S[t][1] - m0); ls0 += S[t][1];
            EX2(S[t][2], S[t][2] - m1); ls1 += S[t][2];
            EX2(S[t][3], S[t][3] - m1); ls1 += S[t][3];
        }
        ls0 += __shfl_xor_sync(0xffffffffu, ls0, 1);
        ls0 += __shfl_xor_sync(0xffffffffu, ls0, 2);
        ls1 += __shfl_xor_sync(0xffffffffu, ls1, 1);
        ls1 += __shfl_xor_sync(0xffffffffu, ls1, 2);
        l0 = l0 * scl0 + ls0;
        l1 = l1 * scl1 + ls1;
#pragma unroll
        for (int t = 0; t < 8; t++) {
            O[t][0] *= scl0; O[t][1] *= scl0;
            O[t][2] *= scl1; O[t][3] *= scl1;
        }

#pragma unroll
        for (int cch = 0; cch < 4; cch++) {
            uint32_t a[4];
            a[0] = f22h(S[2 * cch][0],     S[2 * cch][1]);
            a[1] = f22h(S[2 * cch][2],     S[2 * cch][3]);
            a[2] = f22h(S[2 * cch + 1][0], S[2 * cch + 1][1]);
            a[3] = f22h(S[2 * cch + 1][2], S[2 * cch + 1][3]);
#pragma unroll
            for (int np = 0; np < 4; np++) {
                uint32_t r0, r1, r2, r3;
                LDSMT4(r0, r1, r2, r3,
                       Vb + ((cch * 16 + (lj & 1) * 8 + lr) * SST + np * 16 + (lj >> 1) * 8) * 2);
                uint32_t bA[2] = {r0, r1}, bB[2] = {r2, r3};
                MMAF16(O[2 * np], a, bA);
                MMAF16(O[2 * np + 1], a, bB);
            }
        }
        __syncthreads();
    }

    // normalize, write ctx as fp16 hi/lo
    const float inv0 = 1.f / l0, inv1 = 1.f / l1;
    const int r0g = qt * 64 + w * 16 + q4, r1g = r0g + 8;
#pragma unroll
    for (int t = 0; t < 8; t++) {
        const int dh = t * 8 + q2;
        const size_t base0 = ((size_t)b * SEQ + r0g) * DMODEL + h * HEADDIM + dh;
        const size_t base1 = ((size_t)b * SEQ + r1g) * DMODEL + h * HEADDIM + dh;
        float v0 = O[t][0] * inv0, v1 = O[t][1] * inv0;
        float v2 = O[t][2] * inv1, v3 = O[t][3] * inv1;
        __half h0 = __float2half_rn(v0), h1 = __float2half_rn(v1);
        __half h2 = __float2half_rn(v2), h3 = __float2half_rn(v3);
        *(__half2*)(g_ctx_hi + base0) = __half2(h0, h1);
        *(__half2*)(g_ctx_hi + base1) = __half2(h2, h3);
        *(__half2*)(g_ctx_lo + base0) = __half2(
            __float2half_rn(v0 - __half2float(h0)), __float2half_rn(v1 - __half2float(h1)));
        *(__half2*)(g_ctx_lo + base1) = __half2(
            __float2half_rn(v2 - __half2float(h2)), __float2half_rn(v3 - __half2float(h3)));
    }
}

extern "C" void kernel_launch(void* const* d_in, const int* in_sizes, int n_in,
                              void* d_out, int out_size)
{
    (void)in_sizes; (void)n_in; (void)out_size;
    const float* Q  = (const float*)d_in[0];
    const float* K  = (const float*)d_in[1];
    const float* V  = (const float*)d_in[2];
    const float* Wq = (const float*)d_in[5];
    const float* bq = (const float*)d_in[6];
    const float* Wk = (const float*)d_in[7];
    const float* bk = (const float*)d_in[8];
    const float* Wv = (const float*)d_in[9];
    const float* bv = (const float*)d_in[10];
    const float* Wo = (const float*)d_in[11];
    const float* bo = (const float*)d_in[12];
    float* out = (float*)d_out;

    cudaFuncSetAttribute(gemm_mma_kernel, cudaFuncAttributeMaxDynamicSharedMemorySize, G_SMEM);
    cudaFuncSetAttribute(attn_kernel, cudaFuncAttributeMaxDynamicSharedMemorySize, ATTN_SMEM);

    const int ni = MROWS * DMODEL, nw = DMODEL * DMODEL;
    split_kernel<<<512, 256>>>(Q, 0, ni);
    split_kernel<<<512, 256>>>(K, 1, ni);
    split_kernel<<<512, 256>>>(V, 2, ni);
    split_kernel<<<256, 256>>>(Wq, 3, nw);
    split_kernel<<<256, 256>>>(Wk, 4, nw);
    split_kernel<<<256, 256>>>(Wv, 5, nw);
    split_kernel<<<256, 256>>>(Wo, 6, nw);

    dim3 gg(DMODEL / 128, MROWS / 128);   // (8, 32)
    gemm_mma_kernel<<<gg, 256, G_SMEM>>>(bq, nullptr, 0);
    gemm_mma_kernel<<<gg, 256, G_SMEM>>>(bk, nullptr, 1);
    gemm_mma_kernel<<<gg, 256, G_SMEM>>>(bv, nullptr, 2);
    attn_kernel<<<dim3(SEQ / 64, BH), 128, ATTN_SMEM>>>();
    gemm_mma_kernel<<<gg, 256, G_SMEM>>>(bo, out, 3);
}

// round 10
// speedup vs baseline: 8.0815x; 1.3561x over previous
#include <cuda_runtime.h>
#include <cuda_fp16.h>
#include <cstdint>

#define BATCH    2
#define SEQ      2048
#define DMODEL   1024
#define NHEADS   16
#define HEADDIM  64
#define MROWS    (BATCH * SEQ)
#define BH       (BATCH * NHEADS)

__device__ __half g_in[3][MROWS * DMODEL];    // fp16 inputs
__device__ __half g_w[4][DMODEL * DMODEL];    // fp16 weights
__device__ __half g_qh[BH * SEQ * HEADDIM];   // [bh][s][dh], pre-scaled by log2e/8
__device__ __half g_kh[BH * SEQ * HEADDIM];
__device__ __half g_vh[BH * SEQ * HEADDIM];
__device__ __half g_ctx[MROWS * DMODEL];

__device__ __forceinline__ uint32_t smem_u32(const void* p) {
    uint32_t a;
    asm("{ .reg .u64 t; cvta.to.shared.u64 t, %1; cvt.u32.u64 %0, t; }" : "=r"(a) : "l"(p));
    return a;
}
#define CP16(sp, gp)  asm volatile("cp.async.cg.shared.global [%0], [%1], 16;" :: "r"(sp), "l"(gp))
#define CP_COMMIT()   asm volatile("cp.async.commit_group;" ::: "memory")
#define CP_WAIT1()    asm volatile("cp.async.wait_group 1;" ::: "memory")
#define LDSM4(r0, r1, r2, r3, addr) \
    asm volatile("ldmatrix.sync.aligned.m8n8.x4.shared.b16 {%0,%1,%2,%3}, [%4];" \
                 : "=r"(r0), "=r"(r1), "=r"(r2), "=r"(r3) : "r"(addr))
#define LDSMT4(r0, r1, r2, r3, addr) \
    asm volatile("ldmatrix.sync.aligned.m8n8.x4.trans.shared.b16 {%0,%1,%2,%3}, [%4];" \
                 : "=r"(r0), "=r"(r1), "=r"(r2), "=r"(r3) : "r"(addr))
#define MMAF16(c, a, b) \
    asm volatile("mma.sync.aligned.m16n8k16.row.col.f32.f16.f16.f32 " \
                 "{%0,%1,%2,%3}, {%4,%5,%6,%7}, {%8,%9}, {%0,%1,%2,%3};" \
                 : "+f"((c)[0]), "+f"((c)[1]), "+f"((c)[2]), "+f"((c)[3]) \
                 : "r"((a)[0]), "r"((a)[1]), "r"((a)[2]), "r"((a)[3]), \
                   "r"((b)[0]), "r"((b)[1]))
#define EX2(d, x) asm("ex2.approx.f32 %0, %1;" : "=f"(d) : "f"(x))

__device__ __forceinline__ uint32_t f22h(float a, float b) {
    __half2 h = __floats2half2_rn(a, b);
    return *reinterpret_cast<uint32_t*>(&h);
}

// One launch converts all 7 fp32 tensors to fp16. blockIdx.y selects tensor.
__global__ void convert_kernel(const float* __restrict__ Q, const float* __restrict__ K,
                               const float* __restrict__ V, const float* __restrict__ Wq,
                               const float* __restrict__ Wk, const float* __restrict__ Wv,
                               const float* __restrict__ Wo)
{
    const int which = blockIdx.y;
    const float* src;
    __half* dst;
    int n;
    switch (which) {
        case 0: src = Q;  dst = g_in[0]; n = MROWS * DMODEL; break;
        case 1: src = K;  dst = g_in[1]; n = MROWS * DMODEL; break;
        case 2: src = V;  dst = g_in[2]; n = MROWS * DMODEL; break;
        case 3: src = Wq; dst = g_w[0];  n = DMODEL * DMODEL; break;
        case 4: src = Wk; dst = g_w[1];  n = DMODEL * DMODEL; break;
        case 5: src = Wv; dst = g_w[2];  n = DMODEL * DMODEL; break;
        default: src = Wo; dst = g_w[3]; n = DMODEL * DMODEL; break;
    }
    const int stride = gridDim.x * blockDim.x * 4;
    for (int i = (blockIdx.x * blockDim.x + threadIdx.x) * 4; i < n; i += stride) {
        float4 v = *(const float4*)(src + i);
        *(__half2*)(dst + i)     = __floats2half2_rn(v.x, v.y);
        *(__half2*)(dst + i + 2) = __floats2half2_rn(v.z, v.w);
    }
}

// ---------------------------------------------------------------------------
// fp16 single-segment GEMM: D[4096,1024] = A @ W^T + bias.
// CTA 128x128, BK=32, 8 warps (warp 32x64), 3-stage cp.async pipeline.
// Pitch-40 smem rows: conflict-free ldmatrix without swizzle.
// sel 0/1/2: out -> g_qh/g_kh/g_vh fp16 [bh][s][dh] (sel 0 scaled log2e/8);
// sel 3: fp32 out [M,DMODEL].
// ---------------------------------------------------------------------------
#define ASTRIDE 40
#define A_BYTES (128 * ASTRIDE * 2)   // 10240
#define G_STAGE (2 * A_BYTES)         // 20480: A | B
#define G_SMEM  (3 * G_STAGE)         // 61440
#define NKIT    32

__global__ void __launch_bounds__(256, 1) gemm_mma_kernel(
    const float* __restrict__ bias, float* __restrict__ outext, int sel)
{
    extern __shared__ char smem[];
    const uint32_t sbase = smem_u32(smem);
    const int tid = threadIdx.x;
    const int wid = tid >> 5, lane = tid & 31;
    const int wm = (wid & 3) * 32, wn = (wid >> 2) * 64;
    const int bm = blockIdx.y * 128, bn = blockIdx.x * 128;

    const __half* Ah = (sel < 3) ? g_in[sel] : g_ctx;
    const __half* Bh = g_w[sel];

    float c[2][8][4];
#pragma unroll
    for (int i = 0; i < 2; i++)
#pragma unroll
        for (int j = 0; j < 8; j++)
#pragma unroll
            for (int q = 0; q < 4; q++) c[i][j][q] = 0.f;

    auto fill = [&](int kit) {
        const int st = kit % 3, kk = kit * 32;
        const uint32_t ab = sbase + st * G_STAGE;
        const uint32_t bb = ab + A_BYTES;
#pragma unroll
        for (int t = 0; t < 2; t++) {
            const int id = tid + t * 256;
            const int r = id >> 2, cc = (id & 3) * 8;
            const uint32_t so = (r * ASTRIDE + cc) * 2;
            CP16(ab + so, Ah + (size_t)(bm + r) * DMODEL + kk + cc);
            CP16(bb + so, Bh + (size_t)(bn + r) * DMODEL + kk + cc);
        }
    };

    fill(0); CP_COMMIT();
    fill(1); CP_COMMIT();

    const int lj = lane >> 3, lr = lane & 7;
    const int a_ro = (lj & 1) * 8 + lr, a_co = (lj >> 1) * 8;
    const int b_no = (lj >> 1) * 8 + lr, b_co = (lj & 1) * 8;

    for (int kit = 0; kit < NKIT; kit++) {
        CP_WAIT1();
        __syncthreads();
        if (kit + 2 < NKIT) fill(kit + 2);
        CP_COMMIT();
        const uint32_t ab = sbase + (kit % 3) * G_STAGE;
        const uint32_t bb = ab + A_BYTES;
#pragma unroll
        for (int k16 = 0; k16 < 2; k16++) {
            uint32_t a[2][4];
#pragma unroll
            for (int mt = 0; mt < 2; mt++)
                LDSM4(a[mt][0], a[mt][1], a[mt][2], a[mt][3],
                      ab + ((wm + mt * 16 + a_ro) * ASTRIDE + k16 * 16 + a_co) * 2);
            uint32_t bf[8][2];
#pragma unroll
            for (int np = 0; np < 4; np++) {
                uint32_t r0, r1, r2, r3;
                LDSM4(r0, r1, r2, r3,
                      bb + ((wn + np * 16 + b_no) * ASTRIDE + k16 * 16 + b_co) * 2);
                bf[2 * np][0] = r0; bf[2 * np][1] = r1;
                bf[2 * np + 1][0] = r2; bf[2 * np + 1][1] = r3;
            }
#pragma unroll
            for (int mt = 0; mt < 2; mt++)
#pragma unroll
                for (int nt = 0; nt < 8; nt++)
                    MMAF16(c[mt][nt], a[mt], bf[nt]);
        }
    }

    const float oscale = (sel == 0) ? 0.18033688011112042f : 1.0f;  // log2e/8 folded into Q
    __half* outh = (sel == 0) ? g_qh : (sel == 1) ? g_kh : g_vh;
#pragma unroll
    for (int mt = 0; mt < 2; mt++) {
#pragma unroll
        for (int nt = 0; nt < 8; nt++) {
            const int n0 = bn + wn + nt * 8 + 2 * (lane & 3);
            const float2 bv = *(const float2*)(bias + n0);
#pragma unroll
            for (int half = 0; half < 2; half++) {
                const int m = bm + wm + mt * 16 + (lane >> 2) + half * 8;
                const float rx = c[mt][nt][2 * half]     + bv.x;
                const float ry = c[mt][nt][2 * half + 1] + bv.y;
                if (sel < 3) {
                    const int b = m >> 11, s2 = m & 2047;
                    const int h = n0 >> 6, dh = n0 & 63;
                    __half2 hv = __floats2half2_rn(rx * oscale, ry * oscale);
                    *(__half2*)(outh + ((size_t)(b * NHEADS + h) * SEQ + s2) * HEADDIM + dh) = hv;
                } else {
                    *(float2*)(outext + (size_t)m * DMODEL + n0) = make_float2(rx, ry);
                }
            }
        }
    }
}

// ---------------------------------------------------------------------------
// fp16 tensor-core causal flash attention (round-8/9 winner; ctx now single fp16).
// ---------------------------------------------------------------------------
#define SST 72
#define ATTN_SMEM (5 * 64 * SST * 2)   // 46080 B

__global__ void __launch_bounds__(128) attn_kernel()
{
    extern __shared__ __half smh[];
    const uint32_t sbase = smem_u32(smh);
    const int qt  = (gridDim.x - 1) - blockIdx.x;   // heavy tiles first
    const int bh  = blockIdx.y;
    const int b   = bh >> 4, h = bh & 15;
    const int tid = threadIdx.x;
    const int w   = tid >> 5, lane = tid & 31;
    const int lj = lane >> 3, lr = lane & 7;
    const int a_ro = (lj & 1) * 8 + lr, a_co = (lj >> 1) * 8;
    const int b_no = (lj >> 1) * 8 + lr, b_co = (lj & 1) * 8;
    const int q4 = lane >> 2, q2 = 2 * (lane & 3);

    const size_t kvoff = (size_t)bh * (SEQ * HEADDIM);
    {
        const __half* qg = g_qh + kvoff + (size_t)qt * 64 * HEADDIM;
#pragma unroll
        for (int it = 0; it < 4; it++) {
            const int id = tid + it * 128, r = id >> 3, ch = id & 7;
            CP16(sbase + (r * SST + ch * 8) * 2, qg + r * 64 + ch * 8);
        }
    }
    auto fillKV = [&](int kt, int st) {
        const __half* kb = g_kh + kvoff + (size_t)kt * 64 * HEADDIM;
        const __half* vb = g_vh + kvoff + (size_t)kt * 64 * HEADDIM;
        const uint32_t kd = sbase + (4608 + st * 9216) * 2;
        const uint32_t vd = sbase + (9216 + st * 9216) * 2;
#pragma unroll
        for (int it = 0; it < 4; it++) {
            const int id = tid + it * 128, r = id >> 3, ch = id & 7;
            CP16(kd + (r * SST + ch * 8) * 2, kb + r * 64 + ch * 8);
            CP16(vd + (r * SST + ch * 8) * 2, vb + r * 64 + ch * 8);
        }
    };
    fillKV(0, 0);
    CP_COMMIT();

    float O[8][4];
#pragma unroll
    for (int t = 0; t < 8; t++)
#pragma unroll
        for (int i = 0; i < 4; i++) O[t][i] = 0.f;
    float m0 = -1e30f, m1 = -1e30f, l0 = 0.f, l1 = 0.f;

    for (int kt = 0; kt <= qt; kt++) {
        const int st = kt & 1;
        if (kt < qt) fillKV(kt + 1, st ^ 1);
        CP_COMMIT();
        CP_WAIT1();
        __syncthreads();
        const uint32_t Kb = sbase + (4608 + st * 9216) * 2;
        const uint32_t Vb = sbase + (9216 + st * 9216) * 2;

        float S[8][4];
#pragma unroll
        for (int t = 0; t < 8; t++)
#pragma unroll
            for (int i = 0; i < 4; i++) S[t][i] = 0.f;
#pragma unroll
        for (int kk = 0; kk < 4; kk++) {
            uint32_t a[4];
            LDSM4(a[0], a[1], a[2], a[3],
                  sbase + ((w * 16 + a_ro) * SST + kk * 16 + a_co) * 2);
#pragma unroll
            for (int np = 0; np < 4; np++) {
                uint32_t r0, r1, r2, r3;
                LDSM4(r0, r1, r2, r3,
                      Kb + ((np * 16 + b_no) * SST + kk * 16 + b_co) * 2);
                uint32_t bA[2] = {r0, r1}, bB[2] = {r2, r3};
                MMAF16(S[2 * np], a, bA);
                MMAF16(S[2 * np + 1], a, bB);
            }
        }

        if (kt == qt) {
            const int row0 = w * 16 + q4, row1 = row0 + 8;
#pragma unroll
            for (int t = 0; t < 8; t++) {
                const int c0 = t * 8 + q2;
                if (c0     > row0) S[t][0] = -1e30f;
                if (c0 + 1 > row0) S[t][1] = -1e30f;
                if (c0     > row1) S[t][2] = -1e30f;
                if (c0 + 1 > row1) S[t][3] = -1e30f;
            }
        }

        float mx0 = -1e30f, mx1 = -1e30f;
#pragma unroll
        for (int t = 0; t < 8; t++) {
            mx0 = fmaxf(mx0, fmaxf(S[t][0], S[t][1]));
            mx1 = fmaxf(mx1, fmaxf(S[t][2], S[t][3]));
        }
        mx0 = fmaxf(mx0, __shfl_xor_sync(0xffffffffu, mx0, 1));
        mx0 = fmaxf(mx0, __shfl_xor_sync(0xffffffffu, mx0, 2));
        mx1 = fmaxf(mx1, __shfl_xor_sync(0xffffffffu, mx1, 1));
        mx1 = fmaxf(mx1, __shfl_xor_sync(0xffffffffu, mx1, 2));
        const float nm0 = fmaxf(m0, mx0), nm1 = fmaxf(m1, mx1);
        float scl0, scl1;
        EX2(scl0, m0 - nm0);
        EX2(scl1, m1 - nm1);
        m0 = nm0; m1 = nm1;
        float ls0 = 0.f, ls1 = 0.f;
#pragma unroll
        for (int t = 0; t < 8; t++) {
            EX2(S[t][0], S[t][0] - m0); ls0 += S[t][0];
            EX2(S[t][1], S[t][1] - m0); ls0 += S[t][1];
            EX2(S[t][2], S[t][2] - m1); ls1 += S[t][2];
            EX2(S[t][3], S[t][3] - m1); ls1 += S[t][3];
        }
        ls0 += __shfl_xor_sync(0xffffffffu, ls0, 1);
        ls0 += __shfl_xor_sync(0xffffffffu, ls0, 2);
        ls1 += __shfl_xor_sync(0xffffffffu, ls1, 1);
        ls1 += __shfl_xor_sync(0xffffffffu, ls1, 2);
        l0 = l0 * scl0 + ls0;
        l1 = l1 * scl1 + ls1;
#pragma unroll
        for (int t = 0; t < 8; t++) {
            O[t][0] *= scl0; O[t][1] *= scl0;
            O[t][2] *= scl1; O[t][3] *= scl1;
        }

#pragma unroll
        for (int cch = 0; cch < 4; cch++) {
            uint32_t a[4];
            a[0] = f22h(S[2 * cch][0],     S[2 * cch][1]);
            a[1] = f22h(S[2 * cch][2],     S[2 * cch][3]);
            a[2] = f22h(S[2 * cch + 1][0], S[2 * cch + 1][1]);
            a[3] = f22h(S[2 * cch + 1][2], S[2 * cch + 1][3]);
#pragma unroll
            for (int np = 0; np < 4; np++) {
                uint32_t r0, r1, r2, r3;
                LDSMT4(r0, r1, r2, r3,
                       Vb + ((cch * 16 + (lj & 1) * 8 + lr) * SST + np * 16 + (lj >> 1) * 8) * 2);
                uint32_t bA[2] = {r0, r1}, bB[2] = {r2, r3};
                MMAF16(O[2 * np], a, bA);
                MMAF16(O[2 * np + 1], a, bB);
            }
        }
        __syncthreads();
    }

    // normalize, write ctx as fp16
    const float inv0 = 1.f / l0, inv1 = 1.f / l1;
    const int r0g = qt * 64 + w * 16 + q4, r1g = r0g + 8;
#pragma unroll
    for (int t = 0; t < 8; t++) {
        const int dh = t * 8 + q2;
        const size_t base0 = ((size_t)b * SEQ + r0g) * DMODEL + h * HEADDIM + dh;
        const size_t base1 = ((size_t)b * SEQ + r1g) * DMODEL + h * HEADDIM + dh;
        *(__half2*)(g_ctx + base0) = __floats2half2_rn(O[t][0] * inv0, O[t][1] * inv0);
        *(__half2*)(g_ctx + base1) = __floats2half2_rn(O[t][2] * inv1, O[t][3] * inv1);
    }
}

extern "C" void kernel_launch(void* const* d_in, const int* in_sizes, int n_in,
                              void* d_out, int out_size)
{
    (void)in_sizes; (void)n_in; (void)out_size;
    const float* Q  = (const float*)d_in[0];
    const float* K  = (const float*)d_in[1];
    const float* V  = (const float*)d_in[2];
    const float* Wq = (const float*)d_in[5];
    const float* bq = (const float*)d_in[6];
    const float* Wk = (const float*)d_in[7];
    const float* bk = (const float*)d_in[8];
    const float* Wv = (const float*)d_in[9];
    const float* bv = (const float*)d_in[10];
    const float* Wo = (const float*)d_in[11];
    const float* bo = (const float*)d_in[12];
    float* out = (float*)d_out;

    cudaFuncSetAttribute(gemm_mma_kernel, cudaFuncAttributeMaxDynamicSharedMemorySize, G_SMEM);
    cudaFuncSetAttribute(attn_kernel, cudaFuncAttributeMaxDynamicSharedMemorySize, ATTN_SMEM);

    convert_kernel<<<dim3(512, 7), 256>>>(Q, K, V, Wq, Wk, Wv, Wo);

    dim3 gg(DMODEL / 128, MROWS / 128);   // (8, 32)
    gemm_mma_kernel<<<gg, 256, G_SMEM>>>(bq, nullptr, 0);
    gemm_mma_kernel<<<gg, 256, G_SMEM>>>(bk, nullptr, 1);
    gemm_mma_kernel<<<gg, 256, G_SMEM>>>(bv, nullptr, 2);
    attn_kernel<<<dim3(SEQ / 64, BH), 128, ATTN_SMEM>>>();
    gemm_mma_kernel<<<gg, 256, G_SMEM>>>(bo, out, 3);
}

// round 13
// speedup vs baseline: 9.8842x; 1.2231x over previous
#include <cuda_runtime.h>
#include <cuda_fp16.h>
#include <cstdint>

#define BATCH    2
#define SEQ      2048
#define DMODEL   1024
#define NHEADS   16
#define HEADDIM  64
#define MROWS    (BATCH * SEQ)
#define BH       (BATCH * NHEADS)

__device__ __half g_in[3][MROWS * DMODEL];    // fp16 inputs
__device__ __half g_w[4][DMODEL * DMODEL];    // fp16 weights
__device__ __half g_qh[BH * SEQ * HEADDIM];   // [bh][s][dh], pre-scaled by log2e/8
__device__ __half g_kh[BH * SEQ * HEADDIM];
__device__ __half g_vh[BH * SEQ * HEADDIM];
__device__ __half g_ctx[MROWS * DMODEL];

__device__ __forceinline__ uint32_t smem_u32(const void* p) {
    uint32_t a;
    asm("{ .reg .u64 t; cvta.to.shared.u64 t, %1; cvt.u32.u64 %0, t; }" : "=r"(a) : "l"(p));
    return a;
}
#define CP16(sp, gp)  asm volatile("cp.async.cg.shared.global [%0], [%1], 16;" :: "r"(sp), "l"(gp))
#define CP_COMMIT()   asm volatile("cp.async.commit_group;" ::: "memory")
#define CP_WAIT1()    asm volatile("cp.async.wait_group 1;" ::: "memory")
#define LDSM4(r0, r1, r2, r3, addr) \
    asm volatile("ldmatrix.sync.aligned.m8n8.x4.shared.b16 {%0,%1,%2,%3}, [%4];" \
                 : "=r"(r0), "=r"(r1), "=r"(r2), "=r"(r3) : "r"(addr))
#define LDSMT4(r0, r1, r2, r3, addr) \
    asm volatile("ldmatrix.sync.aligned.m8n8.x4.trans.shared.b16 {%0,%1,%2,%3}, [%4];" \
                 : "=r"(r0), "=r"(r1), "=r"(r2), "=r"(r3) : "r"(addr))
#define MMAF16(c, a, b) \
    asm volatile("mma.sync.aligned.m16n8k16.row.col.f32.f16.f16.f32 " \
                 "{%0,%1,%2,%3}, {%4,%5,%6,%7}, {%8,%9}, {%0,%1,%2,%3};" \
                 : "+f"((c)[0]), "+f"((c)[1]), "+f"((c)[2]), "+f"((c)[3]) \
                 : "r"((a)[0]), "r"((a)[1]), "r"((a)[2]), "r"((a)[3]), \
                   "r"((b)[0]), "r"((b)[1]))
#define EX2(d, x) asm("ex2.approx.f32 %0, %1;" : "=f"(d) : "f"(x))

__device__ __forceinline__ uint32_t f22h(float a, float b) {
    __half2 h = __floats2half2_rn(a, b);
    return *reinterpret_cast<uint32_t*>(&h);
}

// One launch converts all 7 fp32 tensors to fp16. blockIdx.y selects tensor.
__global__ void convert_kernel(const float* __restrict__ Q, const float* __restrict__ K,
                               const float* __restrict__ V, const float* __restrict__ Wq,
                               const float* __restrict__ Wk, const float* __restrict__ Wv,
                               const float* __restrict__ Wo)
{
    const int which = blockIdx.y;
    const float* src;
    __half* dst;
    int n;
    switch (which) {
        case 0: src = Q;  dst = g_in[0]; n = MROWS * DMODEL; break;
        case 1: src = K;  dst = g_in[1]; n = MROWS * DMODEL; break;
        case 2: src = V;  dst = g_in[2]; n = MROWS * DMODEL; break;
        case 3: src = Wq; dst = g_w[0];  n = DMODEL * DMODEL; break;
        case 4: src = Wk; dst = g_w[1];  n = DMODEL * DMODEL; break;
        case 5: src = Wv; dst = g_w[2];  n = DMODEL * DMODEL; break;
        default: src = Wo; dst = g_w[3]; n = DMODEL * DMODEL; break;
    }
    const int stride = gridDim.x * blockDim.x * 4;
    for (int i = (blockIdx.x * blockDim.x + threadIdx.x) * 4; i < n; i += stride) {
        float4 v = *(const float4*)(src + i);
        *(__half2*)(dst + i)     = __floats2half2_rn(v.x, v.y);
        *(__half2*)(dst + i + 2) = __floats2half2_rn(v.z, v.w);
    }
}

// ---------------------------------------------------------------------------
// fp16 GEMM: D[4096,1024] = A @ W^T + bias.
// CTA 128x128, BK=32, 8 warps, 3-stage cp.async pipeline, pitch-40 smem.
// selArg < 0: sel = blockIdx.z (fused QKV launch, biases b0/b1/b2);
// selArg == 3: out-projection, bias = b0, fp32 out.
// __launch_bounds__(256, 2): cap regs at 128 -> 2 CTAs/SM for latency hiding.
// ---------------------------------------------------------------------------
#define ASTRIDE 40
#define A_BYTES (128 * ASTRIDE * 2)   // 10240
#define G_STAGE (2 * A_BYTES)         // 20480: A | B
#define G_SMEM  (3 * G_STAGE)         // 61440
#define NKIT    32

__global__ void __launch_bounds__(256, 2) gemm_mma_kernel(
    const float* __restrict__ b0, const float* __restrict__ b1,
    const float* __restrict__ b2, float* __restrict__ outext, int selArg)
{
    extern __shared__ char smem[];
    const uint32_t sbase = smem_u32(smem);
    const int sel = (selArg < 0) ? (int)blockIdx.z : selArg;
    const float* bias = (sel == 1) ? b1 : (sel == 2) ? b2 : b0;
    const int tid = threadIdx.x;
    const int wid = tid >> 5, lane = tid & 31;
    const int wm = (wid & 3) * 32, wn = (wid >> 2) * 64;
    const int bm = blockIdx.y * 128, bn = blockIdx.x * 128;

    const __half* Ah = (sel < 3) ? g_in[sel] : g_ctx;
    const __half* Bh = g_w[sel];

    float c[2][8][4];
#pragma unroll
    for (int i = 0; i < 2; i++)
#pragma unroll
        for (int j = 0; j < 8; j++)
#pragma unroll
            for (int q = 0; q < 4; q++) c[i][j][q] = 0.f;

    auto fill = [&](int kit) {
        const int st = kit % 3, kk = kit * 32;
        const uint32_t ab = sbase + st * G_STAGE;
        const uint32_t bb = ab + A_BYTES;
#pragma unroll
        for (int t = 0; t < 2; t++) {
            const int id = tid + t * 256;
            const int r = id >> 2, cc = (id & 3) * 8;
            const uint32_t so = (r * ASTRIDE + cc) * 2;
            CP16(ab + so, Ah + (size_t)(bm + r) * DMODEL + kk + cc);
            CP16(bb + so, Bh + (size_t)(bn + r) * DMODEL + kk + cc);
        }
    };

    fill(0); CP_COMMIT();
    fill(1); CP_COMMIT();

    const int lj = lane >> 3, lr = lane & 7;
    const int a_ro = (lj & 1) * 8 + lr, a_co = (lj >> 1) * 8;
    const int b_no = (lj >> 1) * 8 + lr, b_co = (lj & 1) * 8;

    for (int kit = 0; kit < NKIT; kit++) {
        CP_WAIT1();
        __syncthreads();
        if (kit + 2 < NKIT) fill(kit + 2);
        CP_COMMIT();
        const uint32_t ab = sbase + (kit % 3) * G_STAGE;
        const uint32_t bb = ab + A_BYTES;
#pragma unroll
        for (int k16 = 0; k16 < 2; k16++) {
            uint32_t a[2][4];
#pragma unroll
            for (int mt = 0; mt < 2; mt++)
                LDSM4(a[mt][0], a[mt][1], a[mt][2], a[mt][3],
                      ab + ((wm + mt * 16 + a_ro) * ASTRIDE + k16 * 16 + a_co) * 2);
            uint32_t bf[8][2];
#pragma unroll
            for (int np = 0; np < 4; np++) {
                uint32_t r0, r1, r2, r3;
                LDSM4(r0, r1, r2, r3,
                      bb + ((wn + np * 16 + b_no) * ASTRIDE + k16 * 16 + b_co) * 2);
                bf[2 * np][0] = r0; bf[2 * np][1] = r1;
                bf[2 * np + 1][0] = r2; bf[2 * np + 1][1] = r3;
            }
#pragma unroll
            for (int mt = 0; mt < 2; mt++)
#pragma unroll
                for (int nt = 0; nt < 8; nt++)
                    MMAF16(c[mt][nt], a[mt], bf[nt]);
        }
    }

    const float oscale = (sel == 0) ? 0.18033688011112042f : 1.0f;  // log2e/8 folded into Q
    __half* outh = (sel == 0) ? g_qh : (sel == 1) ? g_kh : g_vh;
#pragma unroll
    for (int mt = 0; mt < 2; mt++) {
#pragma unroll
        for (int nt = 0; nt < 8; nt++) {
            const int n0 = bn + wn + nt * 8 + 2 * (lane & 3);
            const float2 bv = *(const float2*)(bias + n0);
#pragma unroll
            for (int half = 0; half < 2; half++) {
                const int m = bm + wm + mt * 16 + (lane >> 2) + half * 8;
                const float rx = c[mt][nt][2 * half]     + bv.x;
                const float ry = c[mt][nt][2 * half + 1] + bv.y;
                if (sel < 3) {
                    const int b = m >> 11, s2 = m & 2047;
                    const int h = n0 >> 6, dh = n0 & 63;
                    __half2 hv = __floats2half2_rn(rx * oscale, ry * oscale);
                    *(__half2*)(outh + ((size_t)(b * NHEADS + h) * SEQ + s2) * HEADDIM + dh) = hv;
                } else {
                    *(float2*)(outext + (size_t)m * DMODEL + n0) = make_float2(rx, ry);
                }
            }
        }
    }
}

// ---------------------------------------------------------------------------
// fp16 tensor-core causal flash attention (round-8/9/10 winner, unchanged).
// ---------------------------------------------------------------------------
#define SST 72
#define ATTN_SMEM (5 * 64 * SST * 2)   // 46080 B

__global__ void __launch_bounds__(128) attn_kernel()
{
    extern __shared__ __half smh[];
    const uint32_t sbase = smem_u32(smh);
    const int qt  = (gridDim.x - 1) - blockIdx.x;   // heavy tiles first
    const int bh  = blockIdx.y;
    const int b   = bh >> 4, h = bh & 15;
    const int tid = threadIdx.x;
    const int w   = tid >> 5, lane = tid & 31;
    const int lj = lane >> 3, lr = lane & 7;
    const int a_ro = (lj & 1) * 8 + lr, a_co = (lj >> 1) * 8;
    const int b_no = (lj >> 1) * 8 + lr, b_co = (lj & 1) * 8;
    const int q4 = lane >> 2, q2 = 2 * (lane & 3);

    const size_t kvoff = (size_t)bh * (SEQ * HEADDIM);
    {
        const __half* qg = g_qh + kvoff + (size_t)qt * 64 * HEADDIM;
#pragma unroll
        for (int it = 0; it < 4; it++) {
            const int id = tid + it * 128, r = id >> 3, ch = id & 7;
            CP16(sbase + (r * SST + ch * 8) * 2, qg + r * 64 + ch * 8);
        }
    }
    auto fillKV = [&](int kt, int st) {
        const __half* kb = g_kh + kvoff + (size_t)kt * 64 * HEADDIM;
        const __half* vb = g_vh + kvoff + (size_t)kt * 64 * HEADDIM;
        const uint32_t kd = sbase + (4608 + st * 9216) * 2;
        const uint32_t vd = sbase + (9216 + st * 9216) * 2;
#pragma unroll
        for (int it = 0; it < 4; it++) {
            const int id = tid + it * 128, r = id >> 3, ch = id & 7;
            CP16(kd + (r * SST + ch * 8) * 2, kb + r * 64 + ch * 8);
            CP16(vd + (r * SST + ch * 8) * 2, vb + r * 64 + ch * 8);
        }
    };
    fillKV(0, 0);
    CP_COMMIT();

    float O[8][4];
#pragma unroll
    for (int t = 0; t < 8; t++)
#pragma unroll
        for (int i = 0; i < 4; i++) O[t][i] = 0.f;
    float m0 = -1e30f, m1 = -1e30f, l0 = 0.f, l1 = 0.f;

    for (int kt = 0; kt <= qt; kt++) {
        const int st = kt & 1;
        if (kt < qt) fillKV(kt + 1, st ^ 1);
        CP_COMMIT();
        CP_WAIT1();
        __syncthreads();
        const uint32_t Kb = sbase + (4608 + st * 9216) * 2;
        const uint32_t Vb = sbase + (9216 + st * 9216) * 2;

        float S[8][4];
#pragma unroll
        for (int t = 0; t < 8; t++)
#pragma unroll
            for (int i = 0; i < 4; i++) S[t][i] = 0.f;
#pragma unroll
        for (int kk = 0; kk < 4; kk++) {
            uint32_t a[4];
            LDSM4(a[0], a[1], a[2], a[3],
                  sbase + ((w * 16 + a_ro) * SST + kk * 16 + a_co) * 2);
#pragma unroll
            for (int np = 0; np < 4; np++) {
                uint32_t r0, r1, r2, r3;
                LDSM4(r0, r1, r2, r3,
                      Kb + ((np * 16 + b_no) * SST + kk * 16 + b_co) * 2);
                uint32_t bA[2] = {r0, r1}, bB[2] = {r2, r3};
                MMAF16(S[2 * np], a, bA);
                MMAF16(S[2 * np + 1], a, bB);
            }
        }

        if (kt == qt) {
            const int row0 = w * 16 + q4, row1 = row0 + 8;
#pragma unroll
            for (int t = 0; t < 8; t++) {
                const int c0 = t * 8 + q2;
                if (c0     > row0) S[t][0] = -1e30f;
                if (c0 + 1 > row0) S[t][1] = -1e30f;
                if (c0     > row1) S[t][2] = -1e30f;
                if (c0 + 1 > row1) S[t][3] = -1e30f;
            }
        }

        float mx0 = -1e30f, mx1 = -1e30f;
#pragma unroll
        for (int t = 0; t < 8; t++) {
            mx0 = fmaxf(mx0, fmaxf(S[t][0], S[t][1]));
            mx1 = fmaxf(mx1, fmaxf(S[t][2], S[t][3]));
        }
        mx0 = fmaxf(mx0, __shfl_xor_sync(0xffffffffu, mx0, 1));
        mx0 = fmaxf(mx0, __shfl_xor_sync(0xffffffffu, mx0, 2));
        mx1 = fmaxf(mx1, __shfl_xor_sync(0xffffffffu, mx1, 1));
        mx1 = fmaxf(mx1, __shfl_xor_sync(0xffffffffu, mx1, 2));
        const float nm0 = fmaxf(m0, mx0), nm1 = fmaxf(m1, mx1);
        float scl0, scl1;
        EX2(scl0, m0 - nm0);
        EX2(scl1, m1 - nm1);
        m0 = nm0; m1 = nm1;
        float ls0 = 0.f, ls1 = 0.f;
#pragma unroll
        for (int t = 0; t < 8; t++) {
            EX2(S[t][0], S[t][0] - m0); ls0 += S[t][0];
            EX2(S[t][1], S[t][1] - m0); ls0 += S[t][1];
            EX2(S[t][2], S[t][2] - m1); ls1 += S[t][2];
            EX2(S[t][3], S[t][3] - m1); ls1 += S[t][3];
        }
        ls0 += __shfl_xor_sync(0xffffffffu, ls0, 1);
        ls0 += __shfl_xor_sync(0xffffffffu, ls0, 2);
        ls1 += __shfl_xor_sync(0xffffffffu, ls1, 1);
        ls1 += __shfl_xor_sync(0xffffffffu, ls1, 2);
        l0 = l0 * scl0 + ls0;
        l1 = l1 * scl1 + ls1;
#pragma unroll
        for (int t = 0; t < 8; t++) {
            O[t][0] *= scl0; O[t][1] *= scl0;
            O[t][2] *= scl1; O[t][3] *= scl1;
        }

#pragma unroll
        for (int cch = 0; cch < 4; cch++) {
            uint32_t a[4];
            a[0] = f22h(S[2 * cch][0],     S[2 * cch][1]);
            a[1] = f22h(S[2 * cch][2],     S[2 * cch][3]);
            a[2] = f22h(S[2 * cch + 1][0], S[2 * cch + 1][1]);
            a[3] = f22h(S[2 * cch + 1][2], S[2 * cch + 1][3]);
#pragma unroll
            for (int np = 0; np < 4; np++) {
                uint32_t r0, r1, r2, r3;
                LDSMT4(r0, r1, r2, r3,
                       Vb + ((cch * 16 + (lj & 1) * 8 + lr) * SST + np * 16 + (lj >> 1) * 8) * 2);
                uint32_t bA[2] = {r0, r1}, bB[2] = {r2, r3};
                MMAF16(O[2 * np], a, bA);
                MMAF16(O[2 * np + 1], a, bB);
            }
        }
        __syncthreads();
    }

    const float inv0 = 1.f / l0, inv1 = 1.f / l1;
    const int r0g = qt * 64 + w * 16 + q4, r1g = r0g + 8;
#pragma unroll
    for (int t = 0; t < 8; t++) {
        const int dh = t * 8 + q2;
        const size_t base0 = ((size_t)b * SEQ + r0g) * DMODEL + h * HEADDIM + dh;
        const size_t base1 = ((size_t)b * SEQ + r1g) * DMODEL + h * HEADDIM + dh;
        *(__half2*)(g_ctx + base0) = __floats2half2_rn(O[t][0] * inv0, O[t][1] * inv0);
        *(__half2*)(g_ctx + base1) = __floats2half2_rn(O[t][2] * inv1, O[t][3] * inv1);
    }
}

extern "C" void kernel_launch(void* const* d_in, const int* in_sizes, int n_in,
                              void* d_out, int out_size)
{
    (void)in_sizes; (void)n_in; (void)out_size;
    const float* Q  = (const float*)d_in[0];
    const float* K  = (const float*)d_in[1];
    const float* V  = (const float*)d_in[2];
    const float* Wq = (const float*)d_in[5];
    const float* bq = (const float*)d_in[6];
    const float* Wk = (const float*)d_in[7];
    const float* bk = (const float*)d_in[8];
    const float* Wv = (const float*)d_in[9];
    const float* bv = (const float*)d_in[10];
    const float* Wo = (const float*)d_in[11];
    const float* bo = (const float*)d_in[12];
    float* out = (float*)d_out;

    cudaFuncSetAttribute(gemm_mma_kernel, cudaFuncAttributeMaxDynamicSharedMemorySize, G_SMEM);
    cudaFuncSetAttribute(attn_kernel, cudaFuncAttributeMaxDynamicSharedMemorySize, ATTN_SMEM);

    convert_kernel<<<dim3(512, 7), 256>>>(Q, K, V, Wq, Wk, Wv, Wo);

    dim3 gqkv(DMODEL / 128, MROWS / 128, 3);   // fused QKV: 768 CTAs
    gemm_mma_kernel<<<gqkv, 256, G_SMEM>>>(bq, bk, bv, nullptr, -1);
    attn_kernel<<<dim3(SEQ / 64, BH), 128, ATTN_SMEM>>>();
    dim3 gout(DMODEL / 128, MROWS / 128, 1);
    gemm_mma_kernel<<<gout, 256, G_SMEM>>>(bo, bo, bo, out, 3);
}